// round 1
// baseline (speedup 1.0000x reference)
#include <cuda_runtime.h>

#define TPB 256
#define W_DIM 128   // hidden width
#define D_IN  64    // 16 emb + 32 feat + 16 sh
#define E_DIM 16
#define F_DIM 32

// smem layout (floats):
//  sW0 : 64*128   = 8192
//  sW1 : 128*128  = 16384
//  sW2 : 128*3    = 384
//  sb0 : 128, sb1 : 128, sb2 : 4
//  hbuf: 128*TPB  = 32768
// total = 57988 floats = 231952 bytes (<= 227KB opt-in)
#define SMEM_FLOATS (8192 + 16384 + 384 + 128 + 128 + 4 + 128 * TPB)

__global__ void __launch_bounds__(TPB, 1) vdc_mlp_kernel(
    const float* __restrict__ features,     // [N, 32]
    const float* __restrict__ dirs,         // [C, N, 3]
    const float* __restrict__ embed_table,  // [1000, 16]
    const float* __restrict__ W0,           // [64, 128]
    const float* __restrict__ b0,           // [128]
    const float* __restrict__ W1,           // [128, 128]
    const float* __restrict__ b1,           // [128]
    const float* __restrict__ W2,           // [128, 3]
    const float* __restrict__ b2,           // [3]
    const int*   __restrict__ embed_ids,    // [C]
    const int*   __restrict__ sh_degree_p,  // scalar (may be null)
    float*       __restrict__ out,          // [C, N, 3]
    int C, int N)
{
    extern __shared__ float sm[];
    float* sW0  = sm;
    float* sW1  = sW0 + 8192;
    float* sW2  = sW1 + 16384;
    float* sb0  = sW2 + 384;
    float* sb1  = sb0 + 128;
    float* sb2  = sb1 + 128;
    float* hbuf = sb2 + 4;      // 128 rows x TPB cols

    const int tid = threadIdx.x;

    // cooperative weight load (once per persistent block)
    for (int i = tid; i < 8192;  i += TPB) sW0[i] = W0[i];
    for (int i = tid; i < 16384; i += TPB) sW1[i] = W1[i];
    for (int i = tid; i < 384;   i += TPB) sW2[i] = W2[i];
    if (tid < 128) { sb0[tid] = b0[tid]; sb1[tid] = b1[tid]; }
    if (tid < 3)   sb2[tid] = b2[tid];

    int deg = 3;
    if (sh_degree_p) deg = *sh_degree_p;
    const int nb_use = (deg + 1) * (deg + 1);
    __syncthreads();

    const int total = C * N;

    for (int base = blockIdx.x * TPB; base < total; base += gridDim.x * TPB) {
        const int p = base + tid;
        const bool active = (p < total);

        // ---------------- build x[64] ----------------
        float x[64];
        if (active) {
            const int c = p / N;
            const int n = p - c * N;

            // camera embedding (broadcast-ish, L1/L2 resident)
            const int id = embed_ids[c];
            const float* er = embed_table + (long)id * E_DIM;
            #pragma unroll
            for (int k = 0; k < 16; k++) x[k] = __ldg(er + k);

            // features row: 8x float4, 128B-aligned
            const float4* fr = (const float4*)(features + (long)n * F_DIM);
            #pragma unroll
            for (int q = 0; q < 8; q++) {
                float4 v = __ldg(fr + q);
                x[16 + 4*q + 0] = v.x; x[16 + 4*q + 1] = v.y;
                x[16 + 4*q + 2] = v.z; x[16 + 4*q + 3] = v.w;
            }

            // dirs -> normalize -> SH bases (gsplat order/constants)
            const float dx = dirs[(long)p*3 + 0];
            const float dy = dirs[(long)p*3 + 1];
            const float dz = dirs[(long)p*3 + 2];
            float nrm = sqrtf(dx*dx + dy*dy + dz*dz);
            float inv = 1.0f / fmaxf(nrm, 1e-12f);
            const float sx = dx * inv, sy = dy * inv, sz = dz * inv;

            const float z2     = sz * sz;
            const float fTmp0B = -1.092548430592079f * sz;
            const float fC1    = sx * sx - sy * sy;
            const float fS1    = 2.0f * sx * sy;
            const float fTmp0C = -2.285228997322329f * z2 + 0.4570457994644658f;
            const float fTmp1B = 1.445305721320277f * sz;
            const float fC2    = sx * fC1 - sy * fS1;
            const float fS2    = sx * fS1 + sy * fC1;

            float sh[16];
            sh[0]  = 0.2820947917738781f;
            sh[1]  = -0.48860251190292f * sy;
            sh[2]  =  0.48860251190292f * sz;
            sh[3]  = -0.48860251190292f * sx;
            sh[4]  =  0.5462742152960395f * fS1;
            sh[5]  =  fTmp0B * sy;
            sh[6]  =  0.9461746957575601f * z2 - 0.3153915652525201f;
            sh[7]  =  fTmp0B * sx;
            sh[8]  =  0.5462742152960395f * fC1;
            sh[9]  = -0.5900435899266435f * fS2;
            sh[10] =  fTmp1B * fS1;
            sh[11] =  fTmp0C * sy;
            sh[12] =  sz * (1.865881662950577f * z2 - 1.119528997770346f);
            sh[13] =  fTmp0C * sx;
            sh[14] =  fTmp1B * fC1;
            sh[15] = -0.5900435899266435f * fC2;

            #pragma unroll
            for (int k = 0; k < 16; k++)
                x[48 + k] = (k < nb_use) ? sh[k] : 0.0f;
        } else {
            #pragma unroll
            for (int k = 0; k < 64; k++) x[k] = 0.0f;
        }

        // ---------------- layer 0: 64 -> 128, relu, to smem ----------------
        for (int t = 0; t < 4; t++) {              // 4 output tiles of 32
            const int i0 = t * 32;
            float acc[32];
            #pragma unroll
            for (int k = 0; k < 32; k++) acc[k] = sb0[i0 + k];
            #pragma unroll
            for (int j = 0; j < 64; j++) {         // must unroll: x[j] in regs
                const float xj = x[j];
                const float4* wr = (const float4*)(sW0 + j * 128 + i0);
                #pragma unroll
                for (int q = 0; q < 8; q++) {
                    float4 w = wr[q];              // broadcast LDS.128
                    acc[4*q+0] += xj * w.x; acc[4*q+1] += xj * w.y;
                    acc[4*q+2] += xj * w.z; acc[4*q+3] += xj * w.w;
                }
            }
            #pragma unroll
            for (int k = 0; k < 32; k++)
                hbuf[(i0 + k) * TPB + tid] = fmaxf(acc[k], 0.0f);
        }
        // NOTE: hbuf column is private per thread -> no __syncthreads needed.

        // ------- layer 1: 128 -> 128, relu, fused layer 2: 128 -> 3 -------
        float o0 = sb2[0], o1 = sb2[1], o2 = sb2[2];
        for (int t = 0; t < 4; t++) {
            const int i0 = t * 32;
            float acc[32];
            #pragma unroll
            for (int k = 0; k < 32; k++) acc[k] = sb1[i0 + k];
            #pragma unroll 2
            for (int j = 0; j < 128; j++) {
                const float hj = hbuf[j * TPB + tid];   // lane-consecutive LDS
                const float4* wr = (const float4*)(sW1 + j * 128 + i0);
                #pragma unroll
                for (int q = 0; q < 8; q++) {
                    float4 w = wr[q];                    // broadcast LDS.128
                    acc[4*q+0] += hj * w.x; acc[4*q+1] += hj * w.y;
                    acc[4*q+2] += hj * w.z; acc[4*q+3] += hj * w.w;
                }
            }
            #pragma unroll
            for (int k = 0; k < 32; k++) {
                const float h1 = fmaxf(acc[k], 0.0f);
                const float* w2 = sW2 + (i0 + k) * 3;   // broadcast
                o0 += h1 * w2[0];
                o1 += h1 * w2[1];
                o2 += h1 * w2[2];
            }
        }

        if (active) {
            out[(long)p*3 + 0] = o0;
            out[(long)p*3 + 1] = o1;
            out[(long)p*3 + 2] = o2;
        }
    }
}

extern "C" void kernel_launch(void* const* d_in, const int* in_sizes, int n_in,
                              void* d_out, int out_size)
{
    const float* features    = (const float*)d_in[0];
    const float* dirs        = (const float*)d_in[1];
    const float* embed_table = (const float*)d_in[2];
    const float* W0          = (const float*)d_in[3];
    const float* b0          = (const float*)d_in[4];
    const float* W1          = (const float*)d_in[5];
    const float* b1          = (const float*)d_in[6];
    const float* W2          = (const float*)d_in[7];
    const float* b2          = (const float*)d_in[8];
    const int*   embed_ids   = (const int*)d_in[9];
    const int*   sh_degree_p = (n_in > 10) ? (const int*)d_in[10] : nullptr;
    float* out = (float*)d_out;

    const int C = in_sizes[9];                 // embed_ids length
    const int N = in_sizes[1] / (3 * C);       // dirs is [C, N, 3]

    int dev = 0, sms = 148;
    cudaGetDevice(&dev);
    cudaDeviceGetAttribute(&sms, cudaDevAttrMultiProcessorCount, dev);

    const size_t smem_bytes = (size_t)SMEM_FLOATS * sizeof(float);
    cudaFuncSetAttribute(vdc_mlp_kernel,
                         cudaFuncAttributeMaxDynamicSharedMemorySize,
                         (int)smem_bytes);

    vdc_mlp_kernel<<<sms, TPB, smem_bytes>>>(
        features, dirs, embed_table, W0, b0, W1, b1, W2, b2,
        embed_ids, sh_degree_p, out, C, N);
}

// round 2
// speedup vs baseline: 1.1128x; 1.1128x over previous
#include <cuda_runtime.h>

#define TPB 256
#define E_DIM 16
#define F_DIM 32

// smem floats: W0 8192 + W1 16384 + W2 384 + b0 128 + b1 128 + b2 4 + hbuf 128*TPB
#define SMEM_FLOATS (8192 + 16384 + 384 + 128 + 128 + 4 + 128 * TPB)

typedef unsigned long long u64;

__device__ __forceinline__ void ffma2(u64& d, u64 a, u64 b) {
    asm("fma.rn.f32x2 %0, %1, %2, %0;" : "+l"(d) : "l"(a), "l"(b));
}
__device__ __forceinline__ u64 pack_dup(float v) {
    u64 r;
    unsigned int u = __float_as_uint(v);
    asm("mov.b64 %0, {%1, %1};" : "=l"(r) : "r"(u));
    return r;
}
__device__ __forceinline__ void unpack2(u64 v, float& lo, float& hi) {
    unsigned int a, b;
    asm("mov.b64 {%0, %1}, %2;" : "=r"(a), "=r"(b) : "l"(v));
    lo = __uint_as_float(a); hi = __uint_as_float(b);
}

__global__ void __launch_bounds__(TPB, 1) vdc_mlp_kernel(
    const float* __restrict__ features,     // [N, 32]
    const float* __restrict__ dirs,         // [C, N, 3]
    const float* __restrict__ embed_table,  // [1000, 16]
    const float* __restrict__ W0,           // [64, 128]
    const float* __restrict__ b0,           // [128]
    const float* __restrict__ W1,           // [128, 128]
    const float* __restrict__ b1,           // [128]
    const float* __restrict__ W2,           // [128, 3]
    const float* __restrict__ b2,           // [3]
    const int*   __restrict__ embed_ids,    // [C]
    const int*   __restrict__ sh_degree_p,  // scalar
    float*       __restrict__ out,          // [C, N, 3]
    int C, int N)
{
    extern __shared__ float sm[];
    float* sW0  = sm;
    float* sW1  = sW0 + 8192;
    float* sW2  = sW1 + 16384;
    float* sb0  = sW2 + 384;
    float* sb1  = sb0 + 128;
    float* sb2  = sb1 + 128;
    float* hbuf = sb2 + 4;      // 128 rows x TPB cols

    const int tid = threadIdx.x;

    for (int i = tid; i < 8192;  i += TPB) sW0[i] = W0[i];
    for (int i = tid; i < 16384; i += TPB) sW1[i] = W1[i];
    for (int i = tid; i < 384;   i += TPB) sW2[i] = W2[i];
    if (tid < 128) { sb0[tid] = b0[tid]; sb1[tid] = b1[tid]; }
    if (tid < 3)   sb2[tid] = b2[tid];

    int deg = 3;
    if (sh_degree_p) deg = *sh_degree_p;
    const int nb_use = (deg + 1) * (deg + 1);
    __syncthreads();

    const int total = C * N;

    for (int base = blockIdx.x * TPB; base < total; base += gridDim.x * TPB) {
        const int p = base + tid;
        const bool active = (p < total);

        // ---------------- build x[64] ----------------
        float x[64];
        if (active) {
            const int c = p / N;
            const int n = p - c * N;

            const int id = embed_ids[c];
            const float* er = embed_table + (long)id * E_DIM;
            #pragma unroll
            for (int k = 0; k < 16; k++) x[k] = __ldg(er + k);

            const float4* fr = (const float4*)(features + (long)n * F_DIM);
            #pragma unroll
            for (int q = 0; q < 8; q++) {
                float4 v = __ldg(fr + q);
                x[16 + 4*q + 0] = v.x; x[16 + 4*q + 1] = v.y;
                x[16 + 4*q + 2] = v.z; x[16 + 4*q + 3] = v.w;
            }

            const float dx = dirs[(long)p*3 + 0];
            const float dy = dirs[(long)p*3 + 1];
            const float dz = dirs[(long)p*3 + 2];
            float nrm = sqrtf(dx*dx + dy*dy + dz*dz);
            float inv = 1.0f / fmaxf(nrm, 1e-12f);
            const float sx = dx * inv, sy = dy * inv, sz = dz * inv;

            const float z2     = sz * sz;
            const float fTmp0B = -1.092548430592079f * sz;
            const float fC1    = sx * sx - sy * sy;
            const float fS1    = 2.0f * sx * sy;
            const float fTmp0C = -2.285228997322329f * z2 + 0.4570457994644658f;
            const float fTmp1B = 1.445305721320277f * sz;
            const float fC2    = sx * fC1 - sy * fS1;
            const float fS2    = sx * fS1 + sy * fC1;

            float sh[16];
            sh[0]  = 0.2820947917738781f;
            sh[1]  = -0.48860251190292f * sy;
            sh[2]  =  0.48860251190292f * sz;
            sh[3]  = -0.48860251190292f * sx;
            sh[4]  =  0.5462742152960395f * fS1;
            sh[5]  =  fTmp0B * sy;
            sh[6]  =  0.9461746957575601f * z2 - 0.3153915652525201f;
            sh[7]  =  fTmp0B * sx;
            sh[8]  =  0.5462742152960395f * fC1;
            sh[9]  = -0.5900435899266435f * fS2;
            sh[10] =  fTmp1B * fS1;
            sh[11] =  fTmp0C * sy;
            sh[12] =  sz * (1.865881662950577f * z2 - 1.119528997770346f);
            sh[13] =  fTmp0C * sx;
            sh[14] =  fTmp1B * fC1;
            sh[15] = -0.5900435899266435f * fC2;

            #pragma unroll
            for (int k = 0; k < 16; k++)
                x[48 + k] = (k < nb_use) ? sh[k] : 0.0f;
        } else {
            #pragma unroll
            for (int k = 0; k < 64; k++) x[k] = 0.0f;
        }

        // -------- layer 0: 64 -> 128, relu, to smem (packed f32x2) --------
        for (int t = 0; t < 4; t++) {
            const int i0 = t * 32;
            u64 acc[16];
            {
                const u64* pb = (const u64*)(sb0 + i0);
                #pragma unroll
                for (int k = 0; k < 16; k++) acc[k] = pb[k];
            }
            #pragma unroll
            for (int j = 0; j < 64; j++) {
                const u64 xx = pack_dup(x[j]);
                const ulonglong2* wr = (const ulonglong2*)(sW0 + j * 128 + i0);
                #pragma unroll
                for (int q = 0; q < 8; q++) {
                    ulonglong2 w = wr[q];          // LDS.128 broadcast
                    ffma2(acc[2*q + 0], xx, w.x);
                    ffma2(acc[2*q + 1], xx, w.y);
                }
            }
            #pragma unroll
            for (int k = 0; k < 16; k++) {
                float lo, hi;
                unpack2(acc[k], lo, hi);
                hbuf[(i0 + 2*k + 0) * TPB + tid] = fmaxf(lo, 0.0f);
                hbuf[(i0 + 2*k + 1) * TPB + tid] = fmaxf(hi, 0.0f);
            }
        }
        // hbuf column private per thread -> no syncthreads.

        // ---- layer 1: 128 -> 128, relu, fused layer 2: 128 -> 3 ----
        float o0 = sb2[0], o1 = sb2[1], o2 = sb2[2];
        for (int t = 0; t < 4; t++) {
            const int i0 = t * 32;
            u64 acc[16];
            {
                const u64* pb = (const u64*)(sb1 + i0);
                #pragma unroll
                for (int k = 0; k < 16; k++) acc[k] = pb[k];
            }
            #pragma unroll 8
            for (int j = 0; j < 128; j++) {
                const u64 hh = pack_dup(hbuf[j * TPB + tid]);  // lane-consecutive
                const ulonglong2* wr = (const ulonglong2*)(sW1 + j * 128 + i0);
                #pragma unroll
                for (int q = 0; q < 8; q++) {
                    ulonglong2 w = wr[q];
                    ffma2(acc[2*q + 0], hh, w.x);
                    ffma2(acc[2*q + 1], hh, w.y);
                }
            }
            #pragma unroll
            for (int k = 0; k < 16; k++) {
                float lo, hi;
                unpack2(acc[k], lo, hi);
                const float h1a = fmaxf(lo, 0.0f);
                const float h1b = fmaxf(hi, 0.0f);
                const float* w2a = sW2 + (i0 + 2*k + 0) * 3;
                const float* w2b = sW2 + (i0 + 2*k + 1) * 3;
                o0 += h1a * w2a[0] + h1b * w2b[0];
                o1 += h1a * w2a[1] + h1b * w2b[1];
                o2 += h1a * w2a[2] + h1b * w2b[2];
            }
        }

        if (active) {
            out[(long)p*3 + 0] = o0;
            out[(long)p*3 + 1] = o1;
            out[(long)p*3 + 2] = o2;
        }
    }
}

extern "C" void kernel_launch(void* const* d_in, const int* in_sizes, int n_in,
                              void* d_out, int out_size)
{
    const float* features    = (const float*)d_in[0];
    const float* dirs        = (const float*)d_in[1];
    const float* embed_table = (const float*)d_in[2];
    const float* W0          = (const float*)d_in[3];
    const float* b0          = (const float*)d_in[4];
    const float* W1          = (const float*)d_in[5];
    const float* b1          = (const float*)d_in[6];
    const float* W2          = (const float*)d_in[7];
    const float* b2          = (const float*)d_in[8];
    const int*   embed_ids   = (const int*)d_in[9];
    const int*   sh_degree_p = (n_in > 10) ? (const int*)d_in[10] : nullptr;
    float* out = (float*)d_out;

    const int C = in_sizes[9];
    const int N = in_sizes[1] / (3 * C);

    int dev = 0, sms = 148;
    cudaGetDevice(&dev);
    cudaDeviceGetAttribute(&sms, cudaDevAttrMultiProcessorCount, dev);

    const size_t smem_bytes = (size_t)SMEM_FLOATS * sizeof(float);
    cudaFuncSetAttribute(vdc_mlp_kernel,
                         cudaFuncAttributeMaxDynamicSharedMemorySize,
                         (int)smem_bytes);

    vdc_mlp_kernel<<<sms, TPB, smem_bytes>>>(
        features, dirs, embed_table, W0, b0, W1, b1, W2, b2,
        embed_ids, sh_degree_p, out, C, N);
}

// round 4
// speedup vs baseline: 2.4670x; 2.2168x over previous
#include <cuda_runtime.h>
#include <cuda_bf16.h>
#include <cstdint>

#define THREADS 256
#define WARPS   8
#define TILE_M  16
#define RS_X    36      // x-stage row stride (u32 words), ≡4 mod 32 -> conflict-free frags
#define RS_H    68      // h-stage row stride, ≡4 mod 32

// ---- smem layout (u32 units) ----
#define U_BIAS0 0                          // 128 floats
#define U_BIAS1 128
#define U_BIAS2 256                        // 8 floats
#define U_BF0   264                        // 2048 uint4  (byte off 1056, %16==0)
#define U_BF1   (U_BF0 + 2048*4)           // 4096 uint4
#define U_BF2   (U_BF1 + 4096*4)           // 256 uint4
#define U_XBUF  (U_BF2 + 256*4)            // 8 warps * 2 * 16*RS_X
#define U_HBUF  (U_XBUF + WARPS*2*16*RS_X)
#define U_TOTAL (U_HBUF + WARPS*2*16*RS_H) // 52488 u32 = 209952 B

__device__ __forceinline__ void mma_bf16(float c[4], const uint32_t a[4],
                                         uint32_t b0, uint32_t b1) {
    asm("mma.sync.aligned.m16n8k16.row.col.f32.bf16.bf16.f32 "
        "{%0,%1,%2,%3}, {%4,%5,%6,%7}, {%8,%9}, {%0,%1,%2,%3};"
        : "+f"(c[0]), "+f"(c[1]), "+f"(c[2]), "+f"(c[3])
        : "r"(a[0]), "r"(a[1]), "r"(a[2]), "r"(a[3]), "r"(b0), "r"(b1));
}

// pack two fp32 -> bf16x2 (rn); low half = first arg
__device__ __forceinline__ uint32_t pack_rn_bf16x2(float lo_elem, float hi_elem) {
    uint32_t r;
    asm("cvt.rn.bf16x2.f32 %0, %1, %2;" : "=r"(r) : "f"(hi_elem), "f"(lo_elem));
    return r;
}

// rn-based hi/lo split for weight staging (one-time cost)
__device__ __forceinline__ void split_rn(float v, uint16_t& h, uint16_t& l) {
    __nv_bfloat16 bh = __float2bfloat16(v);
    float res = v - __bfloat162float(bh);
    __nv_bfloat16 bl = __float2bfloat16(res);
    h = __bfloat16_as_ushort(bh);
    l = __bfloat16_as_ushort(bl);
}

// ---- per-layer MMA: C[NT][4] = A(16 x 16*KS) * B; A frags from smem hi/lo bufs ----
template<int NT, int KS, int RS>
__device__ __forceinline__ void layer_mma(float* C,
                                          const uint32_t* __restrict__ ah,
                                          const uint32_t* __restrict__ al,
                                          const uint4*    __restrict__ BF,
                                          int lane) {
    #pragma unroll
    for (int i = 0; i < NT * 4; i++) C[i] = 0.0f;
    const int r  = lane >> 2;
    const int cb = lane & 3;
    #pragma unroll
    for (int s = 0; s < KS; s++) {
        uint32_t AH[4], AL[4];
        const int cw = s * 8 + cb;
        AH[0] = ah[r * RS + cw];        AH[1] = ah[(r + 8) * RS + cw];
        AH[2] = ah[r * RS + cw + 4];    AH[3] = ah[(r + 8) * RS + cw + 4];
        AL[0] = al[r * RS + cw];        AL[1] = al[(r + 8) * RS + cw];
        AL[2] = al[r * RS + cw + 4];    AL[3] = al[(r + 8) * RS + cw + 4];
        #pragma unroll
        for (int j = 0; j < NT; j++) {
            uint4 b = BF[(j * KS + s) * 32 + lane];
            float* c = C + j * 4;
            mma_bf16(c, AH, b.x, b.y);   // Ah*Bh
            mma_bf16(c, AH, b.z, b.w);   // Ah*Bl
            mma_bf16(c, AL, b.x, b.y);   // Al*Bh
        }
    }
}

// ---- bias + relu + hi/lo split + store to h-stage buffers ----
template<int NT, int RS>
__device__ __forceinline__ void act_store(const float* C, const float* __restrict__ bias,
                                          uint32_t* __restrict__ oh,
                                          uint32_t* __restrict__ ol, int lane) {
    const int r  = lane >> 2;
    const int cb = lane & 3;
    #pragma unroll
    for (int j = 0; j < NT; j++) {
        const float2 bb = *(const float2*)(bias + j * 8 + 2 * cb);
        const float* c = C + j * 4;
        float v0 = fmaxf(c[0] + bb.x, 0.0f), v1 = fmaxf(c[1] + bb.y, 0.0f);
        float v2 = fmaxf(c[2] + bb.x, 0.0f), v3 = fmaxf(c[3] + bb.y, 0.0f);
        uint32_t u0 = __float_as_uint(v0), u1 = __float_as_uint(v1);
        uint32_t u2 = __float_as_uint(v2), u3 = __float_as_uint(v3);
        uint32_t h01 = __byte_perm(u0, u1, 0x7632);   // trunc-hi bf16 pair
        uint32_t h23 = __byte_perm(u2, u3, 0x7632);
        float l0 = v0 - __uint_as_float(u0 & 0xFFFF0000u);
        float l1 = v1 - __uint_as_float(u1 & 0xFFFF0000u);
        float l2 = v2 - __uint_as_float(u2 & 0xFFFF0000u);
        float l3 = v3 - __uint_as_float(u3 & 0xFFFF0000u);
        uint32_t lo01 = pack_rn_bf16x2(l0, l1);
        uint32_t lo23 = pack_rn_bf16x2(l2, l3);
        const int w = j * 4 + cb;
        oh[r * RS + w] = h01;  oh[(r + 8) * RS + w] = h23;
        ol[r * RS + w] = lo01; ol[(r + 8) * RS + w] = lo23;
    }
}

__global__ void __launch_bounds__(THREADS, 1) vdc_mlp_mma_kernel(
    const float* __restrict__ features,     // [N, 32]
    const float* __restrict__ dirs,         // [C, N, 3]
    const float* __restrict__ embed_table,  // [1000, 16]
    const float* __restrict__ W0,           // [64, 128]
    const float* __restrict__ b0,
    const float* __restrict__ W1,           // [128, 128]
    const float* __restrict__ b1,
    const float* __restrict__ W2,           // [128, 3]
    const float* __restrict__ b2,
    const int*   __restrict__ embed_ids,    // [C]
    const int*   __restrict__ sh_degree_p,
    float*       __restrict__ out,          // [C, N, 3]
    int C, int N)
{
    extern __shared__ uint32_t sm[];
    float* BIAS0 = (float*)(sm + U_BIAS0);
    float* BIAS1 = (float*)(sm + U_BIAS1);
    float* BIAS2 = (float*)(sm + U_BIAS2);
    uint4* BF0   = (uint4*)(sm + U_BF0);
    uint4* BF1   = (uint4*)(sm + U_BF1);
    uint4* BF2   = (uint4*)(sm + U_BF2);

    const int tid = threadIdx.x;

    // ---------------- one-time staging ----------------
    for (int i = tid; i < 128; i += THREADS) { BIAS0[i] = b0[i]; BIAS1[i] = b1[i]; }
    if (tid < 8) BIAS2[tid] = (tid < 3) ? b2[tid] : 0.0f;

    // B-fragment precompute. Entry index i = (j*KS + s)*32 + lane.
    // frag: n = j*8 + (lane>>2); k0 = s*16 + 2*(lane&3); elements k0,k0+1 (b0), k0+8,k0+9 (b1)
    // uint4 = {b0_hi, b1_hi, b0_lo, b1_lo}
    for (int i = tid; i < 16 * 4 * 32; i += THREADS) {           // layer0: NT=16 KS=4
        int lane = i & 31, js = i >> 5, s = js & 3, j = js >> 2;
        int n = j * 8 + (lane >> 2), k0 = s * 16 + 2 * (lane & 3);
        uint16_t h[4], l[4];
        #pragma unroll
        for (int q = 0; q < 4; q++) {
            int k = k0 + (q >> 1) * 8 + (q & 1);
            split_rn(W0[k * 128 + n], h[q], l[q]);
        }
        uint4 v;
        v.x = (uint32_t)h[0] | ((uint32_t)h[1] << 16);
        v.y = (uint32_t)h[2] | ((uint32_t)h[3] << 16);
        v.z = (uint32_t)l[0] | ((uint32_t)l[1] << 16);
        v.w = (uint32_t)l[2] | ((uint32_t)l[3] << 16);
        BF0[i] = v;
    }
    for (int i = tid; i < 16 * 8 * 32; i += THREADS) {           // layer1: NT=16 KS=8
        int lane = i & 31, js = i >> 5, s = js & 7, j = js >> 3;
        int n = j * 8 + (lane >> 2), k0 = s * 16 + 2 * (lane & 3);
        uint16_t h[4], l[4];
        #pragma unroll
        for (int q = 0; q < 4; q++) {
            int k = k0 + (q >> 1) * 8 + (q & 1);
            split_rn(W1[k * 128 + n], h[q], l[q]);
        }
        uint4 v;
        v.x = (uint32_t)h[0] | ((uint32_t)h[1] << 16);
        v.y = (uint32_t)h[2] | ((uint32_t)h[3] << 16);
        v.z = (uint32_t)l[0] | ((uint32_t)l[1] << 16);
        v.w = (uint32_t)l[2] | ((uint32_t)l[3] << 16);
        BF1[i] = v;
    }
    for (int i = tid; i < 8 * 32; i += THREADS) {                // layer2: NT=1 KS=8, n pad->8
        int lane = i & 31, s = i >> 5;
        int n = lane >> 2, k0 = s * 16 + 2 * (lane & 3);
        uint16_t h[4], l[4];
        #pragma unroll
        for (int q = 0; q < 4; q++) {
            int k = k0 + (q >> 1) * 8 + (q & 1);
            float w = (n < 3) ? W2[k * 3 + n] : 0.0f;
            split_rn(w, h[q], l[q]);
        }
        uint4 v;
        v.x = (uint32_t)h[0] | ((uint32_t)h[1] << 16);
        v.y = (uint32_t)h[2] | ((uint32_t)h[3] << 16);
        v.z = (uint32_t)l[0] | ((uint32_t)l[1] << 16);
        v.w = (uint32_t)l[2] | ((uint32_t)l[3] << 16);
        BF2[i] = v;
    }

    int deg = 3;
    if (sh_degree_p) deg = *sh_degree_p;
    const int nb_use = (deg + 1) * (deg + 1);
    __syncthreads();

    const int warp = tid >> 5;
    const int lane = tid & 31;
    uint32_t* xh = sm + U_XBUF + warp * (2 * 16 * RS_X);
    uint32_t* xl = xh + 16 * RS_X;
    uint32_t* hh = sm + U_HBUF + warp * (2 * 16 * RS_H);
    uint32_t* hl = hh + 16 * RS_H;

    const int total = C * N;
    const int ntiles = (total + TILE_M - 1) / TILE_M;

    for (int tile = blockIdx.x * WARPS + warp; tile < ntiles; tile += gridDim.x * WARPS) {
        // -------- build x: each lane builds half a row (row = lane>>1, half = lane&1) --------
        const int r_pt = lane >> 1;
        const int half = lane & 1;
        const int p = tile * TILE_M + r_pt;
        float v[32];
        if (p < total) {
            const int c = p / N;
            const int n = p - c * N;
            if (half == 0) {
                // k 0..31 = emb[0:16] + feat[0:16]
                const int id = embed_ids[c];
                const float4* er = (const float4*)(embed_table + (long)id * 16);
                #pragma unroll
                for (int q = 0; q < 4; q++) {
                    float4 e = __ldg(er + q);
                    v[4*q+0] = e.x; v[4*q+1] = e.y; v[4*q+2] = e.z; v[4*q+3] = e.w;
                }
                const float4* fr = (const float4*)(features + (long)n * 32);
                #pragma unroll
                for (int q = 0; q < 4; q++) {
                    float4 f = __ldg(fr + q);
                    v[16+4*q+0] = f.x; v[16+4*q+1] = f.y; v[16+4*q+2] = f.z; v[16+4*q+3] = f.w;
                }
            } else {
                // k 32..63 = feat[16:32] + sh[0:16]
                const float4* fr = (const float4*)(features + (long)n * 32);
                #pragma unroll
                for (int q = 0; q < 4; q++) {
                    float4 f = __ldg(fr + 4 + q);
                    v[4*q+0] = f.x; v[4*q+1] = f.y; v[4*q+2] = f.z; v[4*q+3] = f.w;
                }
                const float dx = dirs[(long)p*3 + 0];
                const float dy = dirs[(long)p*3 + 1];
                const float dz = dirs[(long)p*3 + 2];
                float nrm = sqrtf(dx*dx + dy*dy + dz*dz);
                float inv = 1.0f / fmaxf(nrm, 1e-12f);
                const float sx = dx*inv, sy = dy*inv, sz = dz*inv;
                const float z2     = sz * sz;
                const float fTmp0B = -1.092548430592079f * sz;
                const float fC1    = sx*sx - sy*sy;
                const float fS1    = 2.0f * sx * sy;
                const float fTmp0C = -2.285228997322329f * z2 + 0.4570457994644658f;
                const float fTmp1B = 1.445305721320277f * sz;
                const float fC2    = sx*fC1 - sy*fS1;
                const float fS2    = sx*fS1 + sy*fC1;
                float sh[16];
                sh[0]  = 0.2820947917738781f;
                sh[1]  = -0.48860251190292f * sy;
                sh[2]  =  0.48860251190292f * sz;
                sh[3]  = -0.48860251190292f * sx;
                sh[4]  =  0.5462742152960395f * fS1;
                sh[5]  =  fTmp0B * sy;
                sh[6]  =  0.9461746957575601f * z2 - 0.3153915652525201f;
                sh[7]  =  fTmp0B * sx;
                sh[8]  =  0.5462742152960395f * fC1;
                sh[9]  = -0.5900435899266435f * fS2;
                sh[10] =  fTmp1B * fS1;
                sh[11] =  fTmp0C * sy;
                sh[12] =  sz * (1.865881662950577f * z2 - 1.119528997770346f);
                sh[13] =  fTmp0C * sx;
                sh[14] =  fTmp1B * fC1;
                sh[15] = -0.5900435899266435f * fC2;
                #pragma unroll
                for (int k = 0; k < 16; k++) v[16 + k] = (k < nb_use) ? sh[k] : 0.0f;
            }
        } else {
            #pragma unroll
            for (int k = 0; k < 32; k++) v[k] = 0.0f;
        }
        // split + store to x-stage
        {
            const int wbase = r_pt * RS_X + half * 16;
            #pragma unroll
            for (int w = 0; w < 16; w++) {
                float a = v[2*w], b = v[2*w+1];
                uint32_t ua = __float_as_uint(a), ub = __float_as_uint(b);
                xh[wbase + w] = __byte_perm(ua, ub, 0x7632);
                float la = a - __uint_as_float(ua & 0xFFFF0000u);
                float lb = b - __uint_as_float(ub & 0xFFFF0000u);
                xl[wbase + w] = pack_rn_bf16x2(la, lb);
            }
        }
        __syncwarp();

        float Cacc[64];
        // -------- layer 0: 64 -> 128 --------
        layer_mma<16, 4, RS_X>(Cacc, xh, xl, BF0, lane);
        __syncwarp();
        act_store<16, RS_H>(Cacc, BIAS0, hh, hl, lane);
        __syncwarp();

        // -------- layer 1: 128 -> 128 (in-place h buffer) --------
        layer_mma<16, 8, RS_H>(Cacc, hh, hl, BF1, lane);
        __syncwarp();
        act_store<16, RS_H>(Cacc, BIAS1, hh, hl, lane);
        __syncwarp();

        // -------- layer 2: 128 -> 3 (n padded to 8) --------
        float C2[4];
        layer_mma<1, 8, RS_H>(C2, hh, hl, BF2, lane);

        // -------- output --------
        {
            const int r  = lane >> 2;
            const int cb = lane & 3;
            const int p0 = tile * TILE_M + r;
            const int p1 = p0 + 8;
            if (cb == 0) {
                if (p0 < total) {
                    out[(long)p0*3 + 0] = C2[0] + BIAS2[0];
                    out[(long)p0*3 + 1] = C2[1] + BIAS2[1];
                }
                if (p1 < total) {
                    out[(long)p1*3 + 0] = C2[2] + BIAS2[0];
                    out[(long)p1*3 + 1] = C2[3] + BIAS2[1];
                }
            } else if (cb == 1) {
                if (p0 < total) out[(long)p0*3 + 2] = C2[0] + BIAS2[2];
                if (p1 < total) out[(long)p1*3 + 2] = C2[2] + BIAS2[2];
            }
        }
        __syncwarp();
    }
}

extern "C" void kernel_launch(void* const* d_in, const int* in_sizes, int n_in,
                              void* d_out, int out_size)
{
    const float* features    = (const float*)d_in[0];
    const float* dirs        = (const float*)d_in[1];
    const float* embed_table = (const float*)d_in[2];
    const float* W0          = (const float*)d_in[3];
    const float* b0          = (const float*)d_in[4];
    const float* W1          = (const float*)d_in[5];
    const float* b1          = (const float*)d_in[6];
    const float* W2          = (const float*)d_in[7];
    const float* b2          = (const float*)d_in[8];
    const int*   embed_ids   = (const int*)d_in[9];
    const int*   sh_degree_p = (n_in > 10) ? (const int*)d_in[10] : nullptr;
    float* out = (float*)d_out;

    const int C = in_sizes[9];
    const int N = in_sizes[1] / (3 * C);
    const int total = C * N;
    const int ntiles = (total + TILE_M - 1) / TILE_M;
    const int cta_tiles = (ntiles + WARPS - 1) / WARPS;

    int dev = 0, sms = 148;
    cudaGetDevice(&dev);
    cudaDeviceGetAttribute(&sms, cudaDevAttrMultiProcessorCount, dev);
    int grid = sms < cta_tiles ? sms : cta_tiles;

    const size_t smem_bytes = (size_t)U_TOTAL * 4;
    cudaFuncSetAttribute(vdc_mlp_mma_kernel,
                         cudaFuncAttributeMaxDynamicSharedMemorySize, (int)smem_bytes);

    vdc_mlp_mma_kernel<<<grid, THREADS, smem_bytes>>>(
        features, dirs, embed_table, W0, b0, W1, b1, W2, b2,
        embed_ids, sh_degree_p, out, C, N);
}

// round 5
// speedup vs baseline: 3.8899x; 1.5768x over previous
#include <cuda_runtime.h>
#include <cuda_bf16.h>
#include <cstdint>

#define THREADS 256
#define TILE_PTS 32           // points per warp-pair tile
#define PAIRS    4            // warp pairs per CTA
#define RS_X     28           // x-stage row stride (u32), 48 bf16-pairs = 24 words + pad
#define RS_H     68           // h-stage row stride (u32), 64 words + pad, ≡4 mod 32

// ---- smem layout (u32 units) ----
#define U_EBIAS  0                         // 8 cams x 128 floats (b0 + emb@W0[0:16])
#define U_BIAS1  1024                      // 128
#define U_BIAS2  1152                      // 8
#define U_BF0    1160                      // 16*3*32 uint4 = 6144 u32 (byte 4640 %16==0)
#define U_BF1    (U_BF0 + 6144)            // 16*8*32 uint4 = 16384 u32
#define U_BF2    (U_BF1 + 16384)           // 8*32 uint4 = 1024 u32
#define U_XBUF   (U_BF2 + 1024)            // 4 pairs * 32*RS_X*2
#define U_HBUF   (U_XBUF + PAIRS*32*RS_X*2)
#define U_TOTAL  (U_HBUF + PAIRS*32*RS_H*2)   // 49288 u32 = 197152 B

__device__ __forceinline__ void mma_bf16(float c[4], const uint32_t a[4],
                                         uint32_t b0, uint32_t b1) {
    asm("mma.sync.aligned.m16n8k16.row.col.f32.bf16.bf16.f32 "
        "{%0,%1,%2,%3}, {%4,%5,%6,%7}, {%8,%9}, {%0,%1,%2,%3};"
        : "+f"(c[0]), "+f"(c[1]), "+f"(c[2]), "+f"(c[3])
        : "r"(a[0]), "r"(a[1]), "r"(a[2]), "r"(a[3]), "r"(b0), "r"(b1));
}
__device__ __forceinline__ uint32_t pack_rn_bf16x2(float lo_elem, float hi_elem) {
    uint32_t r;
    asm("cvt.rn.bf16x2.f32 %0, %1, %2;" : "=r"(r) : "f"(hi_elem), "f"(lo_elem));
    return r;
}
__device__ __forceinline__ void split_rn(float v, uint16_t& h, uint16_t& l) {
    __nv_bfloat16 bh = __float2bfloat16(v);
    float res = v - __bfloat162float(bh);
    __nv_bfloat16 bl = __float2bfloat16(res);
    h = __bfloat16_as_ushort(bh);
    l = __bfloat16_as_ushort(bl);
}
__device__ __forceinline__ void bar_pair(int id) {
    asm volatile("bar.sync %0, %1;" :: "r"(id), "r"(64) : "memory");
}

// A-frag load for one 16-row m-block at row base rb
__device__ __forceinline__ void load_afrag(uint32_t A[4], const uint32_t* __restrict__ a,
                                           int rb, int r, int cw, int RS) {
    A[0] = a[(rb + r)     * RS + cw];
    A[1] = a[(rb + r + 8) * RS + cw];
    A[2] = a[(rb + r)     * RS + cw + 4];
    A[3] = a[(rb + r + 8) * RS + cw + 4];
}

// C layout: C[m*NT*4 + j*4 + q], m in {0,1} (rows m*16..), j = local col tile
template<int NT, int KS, int RS>
__device__ __forceinline__ void layer_mma32(float* C,
                                            const uint32_t* __restrict__ ah,
                                            const uint32_t* __restrict__ al,
                                            const uint4*    __restrict__ BF,
                                            int lane, int jbase) {
    #pragma unroll
    for (int i = 0; i < 2 * NT * 4; i++) C[i] = 0.0f;
    const int r  = lane >> 2;
    const int cb = lane & 3;
    #pragma unroll
    for (int s = 0; s < KS; s++) {
        const int cw = s * 8 + cb;
        uint32_t A0H[4], A0L[4], A1H[4], A1L[4];
        load_afrag(A0H, ah, 0,  r, cw, RS);
        load_afrag(A0L, al, 0,  r, cw, RS);
        load_afrag(A1H, ah, 16, r, cw, RS);
        load_afrag(A1L, al, 16, r, cw, RS);
        #pragma unroll
        for (int j = 0; j < NT; j++) {
            uint4 b = BF[((jbase + j) * KS + s) * 32 + lane];
            float* c0 = C + j * 4;
            float* c1 = C + (NT + j) * 4;
            mma_bf16(c0, A0H, b.x, b.y);
            mma_bf16(c0, A0H, b.z, b.w);
            mma_bf16(c0, A0L, b.x, b.y);
            mma_bf16(c1, A1H, b.x, b.y);
            mma_bf16(c1, A1H, b.z, b.w);
            mma_bf16(c1, A1L, b.x, b.y);
        }
    }
}

// bias+relu+split+store one acc frag (4 floats) at rows (rA, rA+8), word w
__device__ __forceinline__ void store_frag(const float* c, float bxA, float byA,
                                           float bxB, float byB,
                                           uint32_t* __restrict__ oh,
                                           uint32_t* __restrict__ ol,
                                           int rA, int w, int RS) {
    float v0 = fmaxf(c[0] + bxA, 0.0f), v1 = fmaxf(c[1] + byA, 0.0f);
    float v2 = fmaxf(c[2] + bxB, 0.0f), v3 = fmaxf(c[3] + byB, 0.0f);
    uint32_t u0 = __float_as_uint(v0), u1 = __float_as_uint(v1);
    uint32_t u2 = __float_as_uint(v2), u3 = __float_as_uint(v3);
    oh[rA * RS + w]       = __byte_perm(u0, u1, 0x7632);
    oh[(rA + 8) * RS + w] = __byte_perm(u2, u3, 0x7632);
    float l0 = v0 - __uint_as_float(u0 & 0xFFFF0000u);
    float l1 = v1 - __uint_as_float(u1 & 0xFFFF0000u);
    float l2 = v2 - __uint_as_float(u2 & 0xFFFF0000u);
    float l3 = v3 - __uint_as_float(u3 & 0xFFFF0000u);
    ol[rA * RS + w]       = pack_rn_bf16x2(l0, l1);
    ol[(rA + 8) * RS + w] = pack_rn_bf16x2(l2, l3);
}

__global__ void __launch_bounds__(THREADS, 1) vdc_mlp_mma32_kernel(
    const float* __restrict__ features,     // [N, 32]
    const float* __restrict__ dirs,         // [C, N, 3]
    const float* __restrict__ embed_table,  // [1000, 16]
    const float* __restrict__ W0,           // [64, 128]
    const float* __restrict__ b0,
    const float* __restrict__ W1,           // [128, 128]
    const float* __restrict__ b1,
    const float* __restrict__ W2,           // [128, 3]
    const float* __restrict__ b2,
    const int*   __restrict__ embed_ids,    // [C]
    const int*   __restrict__ sh_degree_p,
    float*       __restrict__ out,          // [C, N, 3]
    int C, int N)
{
    extern __shared__ uint32_t sm[];
    float* EBIAS = (float*)(sm + U_EBIAS);   // [8][128]
    float* BIAS1 = (float*)(sm + U_BIAS1);
    float* BIAS2 = (float*)(sm + U_BIAS2);
    uint4* BF0   = (uint4*)(sm + U_BF0);
    uint4* BF1   = (uint4*)(sm + U_BF1);
    uint4* BF2   = (uint4*)(sm + U_BF2);

    const int tid = threadIdx.x;

    // ---------------- one-time staging ----------------
    for (int i = tid; i < 128; i += THREADS) BIAS1[i] = b1[i];
    if (tid < 8) BIAS2[tid] = (tid < 3) ? b2[tid] : 0.0f;

    // per-camera fused bias: ebias[c] = b0 + emb_c @ W0[0:16,:]
    const int ncb = (C < 8 ? C : 8);
    for (int i = tid; i < ncb * 128; i += THREADS) {
        int c = i >> 7, col = i & 127;
        const float* er = embed_table + (long)embed_ids[c] * 16;
        float s = b0[col];
        #pragma unroll
        for (int k = 0; k < 16; k++) s += __ldg(er + k) * W0[k * 128 + col];
        EBIAS[c * 128 + col] = s;
    }

    // BF0: layer0 (inputs = feat32|sh16 -> W0 rows 16..63), NT=16 global, KS=3
    for (int i = tid; i < 16 * 3 * 32; i += THREADS) {
        int lane = i & 31, js = i >> 5, s = js % 3, j = js / 3;
        int n = j * 8 + (lane >> 2), k0 = s * 16 + 2 * (lane & 3);
        uint16_t h[4], l[4];
        #pragma unroll
        for (int q = 0; q < 4; q++) {
            int k = k0 + (q >> 1) * 8 + (q & 1);
            split_rn(W0[(16 + k) * 128 + n], h[q], l[q]);
        }
        uint4 v;
        v.x = (uint32_t)h[0] | ((uint32_t)h[1] << 16);
        v.y = (uint32_t)h[2] | ((uint32_t)h[3] << 16);
        v.z = (uint32_t)l[0] | ((uint32_t)l[1] << 16);
        v.w = (uint32_t)l[2] | ((uint32_t)l[3] << 16);
        BF0[i] = v;
    }
    // BF1: layer1, KS=8
    for (int i = tid; i < 16 * 8 * 32; i += THREADS) {
        int lane = i & 31, js = i >> 5, s = js & 7, j = js >> 3;
        int n = j * 8 + (lane >> 2), k0 = s * 16 + 2 * (lane & 3);
        uint16_t h[4], l[4];
        #pragma unroll
        for (int q = 0; q < 4; q++) {
            int k = k0 + (q >> 1) * 8 + (q & 1);
            split_rn(W1[k * 128 + n], h[q], l[q]);
        }
        uint4 v;
        v.x = (uint32_t)h[0] | ((uint32_t)h[1] << 16);
        v.y = (uint32_t)h[2] | ((uint32_t)h[3] << 16);
        v.z = (uint32_t)l[0] | ((uint32_t)l[1] << 16);
        v.w = (uint32_t)l[2] | ((uint32_t)l[3] << 16);
        BF1[i] = v;
    }
    // BF2: layer2 (n padded to 8), KS=8
    for (int i = tid; i < 8 * 32; i += THREADS) {
        int lane = i & 31, s = i >> 5;
        int n = lane >> 2, k0 = s * 16 + 2 * (lane & 3);
        uint16_t h[4], l[4];
        #pragma unroll
        for (int q = 0; q < 4; q++) {
            int k = k0 + (q >> 1) * 8 + (q & 1);
            float w = (n < 3) ? W2[k * 3 + n] : 0.0f;
            split_rn(w, h[q], l[q]);
        }
        uint4 v;
        v.x = (uint32_t)h[0] | ((uint32_t)h[1] << 16);
        v.y = (uint32_t)h[2] | ((uint32_t)h[3] << 16);
        v.z = (uint32_t)l[0] | ((uint32_t)l[1] << 16);
        v.w = (uint32_t)l[2] | ((uint32_t)l[3] << 16);
        BF2[i] = v;
    }

    int deg = 3;
    if (sh_degree_p) deg = *sh_degree_p;
    const int nb_use = (deg + 1) * (deg + 1);
    __syncthreads();

    const int warp   = tid >> 5;
    const int lane   = tid & 31;
    const int pairid = warp >> 1;
    const int hw     = warp & 1;          // column half: cols [hw*64, hw*64+64)
    const int barid  = pairid + 1;

    uint32_t* xh = sm + U_XBUF + pairid * (32 * RS_X * 2);
    uint32_t* xl = xh + 32 * RS_X;
    uint32_t* hh = sm + U_HBUF + pairid * (32 * RS_H * 2);
    uint32_t* hl = hh + 32 * RS_H;

    const int total  = C * N;
    const int ntiles = (total + TILE_PTS - 1) / TILE_PTS;

    const int r  = lane >> 2;
    const int cb = lane & 3;

    for (int tile = blockIdx.x * PAIRS + pairid; tile < ntiles; tile += gridDim.x * PAIRS) {
        const int tb = tile * TILE_PTS;

        // -------- x-build: warp builds its 16 rows; lane = (row, half) --------
        {
            const int row  = hw * 16 + (lane >> 1);
            const int half = lane & 1;
            const int p = tb + row;
            float v[24];
            if (p < total) {
                const int c = p / N;
                const int n = p - c * N;
                const float4* fr = (const float4*)(features + (long)n * 32);
                if (half == 0) {
                    #pragma unroll
                    for (int q = 0; q < 6; q++) {
                        float4 f = __ldg(fr + q);
                        v[4*q+0]=f.x; v[4*q+1]=f.y; v[4*q+2]=f.z; v[4*q+3]=f.w;
                    }
                } else {
                    #pragma unroll
                    for (int q = 0; q < 2; q++) {
                        float4 f = __ldg(fr + 6 + q);
                        v[4*q+0]=f.x; v[4*q+1]=f.y; v[4*q+2]=f.z; v[4*q+3]=f.w;
                    }
                    const float dx = dirs[(long)p*3 + 0];
                    const float dy = dirs[(long)p*3 + 1];
                    const float dz = dirs[(long)p*3 + 2];
                    float nrm = sqrtf(dx*dx + dy*dy + dz*dz);
                    float inv = 1.0f / fmaxf(nrm, 1e-12f);
                    const float sx = dx*inv, sy = dy*inv, sz = dz*inv;
                    const float z2     = sz * sz;
                    const float fTmp0B = -1.092548430592079f * sz;
                    const float fC1    = sx*sx - sy*sy;
                    const float fS1    = 2.0f * sx * sy;
                    const float fTmp0C = -2.285228997322329f * z2 + 0.4570457994644658f;
                    const float fTmp1B = 1.445305721320277f * sz;
                    const float fC2    = sx*fC1 - sy*fS1;
                    const float fS2    = sx*fS1 + sy*fC1;
                    float sh[16];
                    sh[0]  = 0.2820947917738781f;
                    sh[1]  = -0.48860251190292f * sy;
                    sh[2]  =  0.48860251190292f * sz;
                    sh[3]  = -0.48860251190292f * sx;
                    sh[4]  =  0.5462742152960395f * fS1;
                    sh[5]  =  fTmp0B * sy;
                    sh[6]  =  0.9461746957575601f * z2 - 0.3153915652525201f;
                    sh[7]  =  fTmp0B * sx;
                    sh[8]  =  0.5462742152960395f * fC1;
                    sh[9]  = -0.5900435899266435f * fS2;
                    sh[10] =  fTmp1B * fS1;
                    sh[11] =  fTmp0C * sy;
                    sh[12] =  sz * (1.865881662950577f * z2 - 1.119528997770346f);
                    sh[13] =  fTmp0C * sx;
                    sh[14] =  fTmp1B * fC1;
                    sh[15] = -0.5900435899266435f * fC2;
                    #pragma unroll
                    for (int k = 0; k < 16; k++) v[8 + k] = (k < nb_use) ? sh[k] : 0.0f;
                }
            } else {
                #pragma unroll
                for (int k = 0; k < 24; k++) v[k] = 0.0f;
            }
            const int wbase = row * RS_X + half * 12;
            #pragma unroll
            for (int w = 0; w < 12; w++) {
                float a = v[2*w], b = v[2*w+1];
                uint32_t ua = __float_as_uint(a), ub = __float_as_uint(b);
                xh[wbase + w] = __byte_perm(ua, ub, 0x7632);
                float la = a - __uint_as_float(ua & 0xFFFF0000u);
                float lb = b - __uint_as_float(ub & 0xFFFF0000u);
                xl[wbase + w] = pack_rn_bf16x2(la, lb);
            }
        }
        bar_pair(barid);                         // x complete

        float Cacc[64];

        // -------- layer 0: 48 -> 128 --------
        layer_mma32<8, 3, RS_X>(Cacc, xh, xl, BF0, lane, hw * 8);

        // act_store with per-camera fused bias
        {
            int pA0 = tb + r;
            int cA0 = pA0 < total ? pA0 / N : 0;
            int cB0 = (pA0 + 8)  < total ? (pA0 + 8)  / N : 0;
            int cA1 = (pA0 + 16) < total ? (pA0 + 16) / N : 0;
            int cB1 = (pA0 + 24) < total ? (pA0 + 24) / N : 0;
            const float* eA0 = EBIAS + cA0 * 128;
            const float* eB0 = EBIAS + cB0 * 128;
            const float* eA1 = EBIAS + cA1 * 128;
            const float* eB1 = EBIAS + cB1 * 128;
            #pragma unroll
            for (int j = 0; j < 8; j++) {
                const int col = (hw * 8 + j) * 8 + 2 * cb;
                const int w   = (hw * 8 + j) * 4 + cb;
                float2 bA0 = *(const float2*)(eA0 + col);
                float2 bB0 = *(const float2*)(eB0 + col);
                store_frag(Cacc + j * 4, bA0.x, bA0.y, bB0.x, bB0.y, hh, hl, r, w, RS_H);
                float2 bA1 = *(const float2*)(eA1 + col);
                float2 bB1 = *(const float2*)(eB1 + col);
                store_frag(Cacc + 32 + j * 4, bA1.x, bA1.y, bB1.x, bB1.y, hh, hl, 16 + r, w, RS_H);
            }
        }
        bar_pair(barid);                         // h0 complete

        // -------- layer 1: 128 -> 128 --------
        layer_mma32<8, 8, RS_H>(Cacc, hh, hl, BF1, lane, hw * 8);
        bar_pair(barid);                         // all h0 reads done
        {
            #pragma unroll
            for (int j = 0; j < 8; j++) {
                const int col = (hw * 8 + j) * 8 + 2 * cb;
                const int w   = (hw * 8 + j) * 4 + cb;
                float2 bb = *(const float2*)(BIAS1 + col);
                store_frag(Cacc + j * 4,      bb.x, bb.y, bb.x, bb.y, hh, hl, r, w, RS_H);
                store_frag(Cacc + 32 + j * 4, bb.x, bb.y, bb.x, bb.y, hh, hl, 16 + r, w, RS_H);
            }
        }
        bar_pair(barid);                         // h1 complete

        // -------- layer 2: 128 -> 3 (n pad 8); warp handles its 16 rows --------
        {
            float C2[4] = {0.f, 0.f, 0.f, 0.f};
            const int rb = hw * 16;
            #pragma unroll
            for (int s = 0; s < 8; s++) {
                const int cw = s * 8 + cb;
                uint32_t AH[4], AL[4];
                load_afrag(AH, hh, rb, r, cw, RS_H);
                load_afrag(AL, hl, rb, r, cw, RS_H);
                uint4 b = BF2[s * 32 + lane];
                mma_bf16(C2, AH, b.x, b.y);
                mma_bf16(C2, AH, b.z, b.w);
                mma_bf16(C2, AL, b.x, b.y);
            }
            const int p0 = tb + rb + r;
            const int p1 = p0 + 8;
            if (cb == 0) {
                if (p0 < total) {
                    out[(long)p0*3 + 0] = C2[0] + BIAS2[0];
                    out[(long)p0*3 + 1] = C2[1] + BIAS2[1];
                }
                if (p1 < total) {
                    out[(long)p1*3 + 0] = C2[2] + BIAS2[0];
                    out[(long)p1*3 + 1] = C2[3] + BIAS2[1];
                }
            } else if (cb == 1) {
                if (p0 < total) out[(long)p0*3 + 2] = C2[0] + BIAS2[2];
                if (p1 < total) out[(long)p1*3 + 2] = C2[2] + BIAS2[2];
            }
        }
        // next iteration's bar A (after x-build) protects h vs next act_store
    }
}

extern "C" void kernel_launch(void* const* d_in, const int* in_sizes, int n_in,
                              void* d_out, int out_size)
{
    const float* features    = (const float*)d_in[0];
    const float* dirs        = (const float*)d_in[1];
    const float* embed_table = (const float*)d_in[2];
    const float* W0          = (const float*)d_in[3];
    const float* b0          = (const float*)d_in[4];
    const float* W1          = (const float*)d_in[5];
    const float* b1          = (const float*)d_in[6];
    const float* W2          = (const float*)d_in[7];
    const float* b2          = (const float*)d_in[8];
    const int*   embed_ids   = (const int*)d_in[9];
    const int*   sh_degree_p = (n_in > 10) ? (const int*)d_in[10] : nullptr;
    float* out = (float*)d_out;

    const int C = in_sizes[9];
    const int N = in_sizes[1] / (3 * C);
    const int total = C * N;
    const int ntiles = (total + TILE_PTS - 1) / TILE_PTS;
    const int cta_tiles = (ntiles + PAIRS - 1) / PAIRS;

    int dev = 0, sms = 148;
    cudaGetDevice(&dev);
    cudaDeviceGetAttribute(&sms, cudaDevAttrMultiProcessorCount, dev);
    int grid = sms < cta_tiles ? sms : cta_tiles;

    const size_t smem_bytes = (size_t)U_TOTAL * 4;
    cudaFuncSetAttribute(vdc_mlp_mma32_kernel,
                         cudaFuncAttributeMaxDynamicSharedMemorySize, (int)smem_bytes);

    vdc_mlp_mma32_kernel<<<grid, THREADS, smem_bytes>>>(
        features, dirs, embed_table, W0, b0, W1, b1, W2, b2,
        embed_ids, sh_degree_p, out, C, N);
}

// round 6
// speedup vs baseline: 4.0265x; 1.0351x over previous
#include <cuda_runtime.h>
#include <cuda_bf16.h>
#include <cstdint>

#define THREADS 384
#define PAIRS    6            // warp pairs per CTA
#define TILE_PTS 32           // points per warp-pair tile
#define RS_X     28           // x-stage row stride (u32), 24 words + pad, ≡28 mod 32
#define RS_H     68           // h-stage row stride (u32), 64 words + pad, ≡4 mod 32

// ---- smem layout (u32 units) ----
#define U_EBIAS  0                         // 8 cams x 128 floats (b0 + emb@W0[0:16])
#define U_BIAS1  1024                      // 128
#define U_BIAS2  1152                      // 8
#define U_BF0    1160                      // 16*3*32 uint4 = 6144 u32 (byte 4640 %16==0)
#define U_BF1    (U_BF0 + 6144)            // 16*8*32 uint4 = 16384 u32
#define U_BF2    (U_BF1 + 16384)           // 8*32 uint4 = 1024 u32
#define U_HBUF   (U_BF2 + 1024)            // 6 pairs * (2176 hi + 2176 lo); x overlays h
#define U_TOTAL  (U_HBUF + PAIRS*2*32*RS_H)   // 50824 u32 = 203296 B

__device__ __forceinline__ void mma_bf16(float c[4], const uint32_t a[4],
                                         uint32_t b0, uint32_t b1) {
    asm("mma.sync.aligned.m16n8k16.row.col.f32.bf16.bf16.f32 "
        "{%0,%1,%2,%3}, {%4,%5,%6,%7}, {%8,%9}, {%0,%1,%2,%3};"
        : "+f"(c[0]), "+f"(c[1]), "+f"(c[2]), "+f"(c[3])
        : "r"(a[0]), "r"(a[1]), "r"(a[2]), "r"(a[3]), "r"(b0), "r"(b1));
}
__device__ __forceinline__ uint32_t pack_rn_bf16x2(float lo_elem, float hi_elem) {
    uint32_t r;
    asm("cvt.rn.bf16x2.f32 %0, %1, %2;" : "=r"(r) : "f"(hi_elem), "f"(lo_elem));
    return r;
}
__device__ __forceinline__ void split_rn(float v, uint16_t& h, uint16_t& l) {
    __nv_bfloat16 bh = __float2bfloat16(v);
    float res = v - __bfloat162float(bh);
    __nv_bfloat16 bl = __float2bfloat16(res);
    h = __bfloat16_as_ushort(bh);
    l = __bfloat16_as_ushort(bl);
}
__device__ __forceinline__ void bar_pair(int id) {
    asm volatile("bar.sync %0, %1;" :: "r"(id), "r"(64) : "memory");
}

__device__ __forceinline__ void load_afrag(uint32_t A[4], const uint32_t* __restrict__ a,
                                           int rb, int r, int cw, int RS) {
    A[0] = a[(rb + r)     * RS + cw];
    A[1] = a[(rb + r + 8) * RS + cw];
    A[2] = a[(rb + r)     * RS + cw + 4];
    A[3] = a[(rb + r + 8) * RS + cw + 4];
}

// C layout: C[m*NT*4 + j*4 + q], m in {0,1} (rows m*16..), j = local col tile
template<int NT, int KS, int RS>
__device__ __forceinline__ void layer_mma32(float* C,
                                            const uint32_t* __restrict__ ah,
                                            const uint32_t* __restrict__ al,
                                            const uint4*    __restrict__ BF,
                                            int lane, int jbase) {
    #pragma unroll
    for (int i = 0; i < 2 * NT * 4; i++) C[i] = 0.0f;
    const int r  = lane >> 2;
    const int cb = lane & 3;
    #pragma unroll
    for (int s = 0; s < KS; s++) {
        const int cw = s * 8 + cb;
        uint32_t A0H[4], A0L[4], A1H[4], A1L[4];
        load_afrag(A0H, ah, 0,  r, cw, RS);
        load_afrag(A0L, al, 0,  r, cw, RS);
        load_afrag(A1H, ah, 16, r, cw, RS);
        load_afrag(A1L, al, 16, r, cw, RS);
        #pragma unroll
        for (int j = 0; j < NT; j++) {
            uint4 b = BF[((jbase + j) * KS + s) * 32 + lane];
            float* c0 = C + j * 4;
            float* c1 = C + (NT + j) * 4;
            mma_bf16(c0, A0H, b.x, b.y);
            mma_bf16(c0, A0H, b.z, b.w);
            mma_bf16(c0, A0L, b.x, b.y);
            mma_bf16(c1, A1H, b.x, b.y);
            mma_bf16(c1, A1H, b.z, b.w);
            mma_bf16(c1, A1L, b.x, b.y);
        }
    }
}

__device__ __forceinline__ void store_frag(const float* c, float bxA, float byA,
                                           float bxB, float byB,
                                           uint32_t* __restrict__ oh,
                                           uint32_t* __restrict__ ol,
                                           int rA, int w, int RS) {
    float v0 = fmaxf(c[0] + bxA, 0.0f), v1 = fmaxf(c[1] + byA, 0.0f);
    float v2 = fmaxf(c[2] + bxB, 0.0f), v3 = fmaxf(c[3] + byB, 0.0f);
    uint32_t u0 = __float_as_uint(v0), u1 = __float_as_uint(v1);
    uint32_t u2 = __float_as_uint(v2), u3 = __float_as_uint(v3);
    oh[rA * RS + w]       = __byte_perm(u0, u1, 0x7632);
    oh[(rA + 8) * RS + w] = __byte_perm(u2, u3, 0x7632);
    float l0 = v0 - __uint_as_float(u0 & 0xFFFF0000u);
    float l1 = v1 - __uint_as_float(u1 & 0xFFFF0000u);
    float l2 = v2 - __uint_as_float(u2 & 0xFFFF0000u);
    float l3 = v3 - __uint_as_float(u3 & 0xFFFF0000u);
    ol[rA * RS + w]       = pack_rn_bf16x2(l0, l1);
    ol[(rA + 8) * RS + w] = pack_rn_bf16x2(l2, l3);
}

__global__ void __launch_bounds__(THREADS, 1) vdc_mlp_mma384_kernel(
    const float* __restrict__ features,     // [N, 32]
    const float* __restrict__ dirs,         // [C, N, 3]
    const float* __restrict__ embed_table,  // [1000, 16]
    const float* __restrict__ W0,           // [64, 128]
    const float* __restrict__ b0,
    const float* __restrict__ W1,           // [128, 128]
    const float* __restrict__ b1,
    const float* __restrict__ W2,           // [128, 3]
    const float* __restrict__ b2,
    const int*   __restrict__ embed_ids,    // [C]
    const int*   __restrict__ sh_degree_p,
    float*       __restrict__ out,          // [C, N, 3]
    int C, int N)
{
    extern __shared__ uint32_t sm[];
    float* EBIAS = (float*)(sm + U_EBIAS);   // [8][128]
    float* BIAS1 = (float*)(sm + U_BIAS1);
    float* BIAS2 = (float*)(sm + U_BIAS2);
    uint4* BF0   = (uint4*)(sm + U_BF0);
    uint4* BF1   = (uint4*)(sm + U_BF1);
    uint4* BF2   = (uint4*)(sm + U_BF2);

    const int tid = threadIdx.x;

    // ---------------- one-time staging ----------------
    for (int i = tid; i < 128; i += THREADS) BIAS1[i] = b1[i];
    if (tid < 8) BIAS2[tid] = (tid < 3) ? b2[tid] : 0.0f;

    // per-camera fused bias: ebias[c] = b0 + emb_c @ W0[0:16,:]
    const int ncb = (C < 8 ? C : 8);
    for (int i = tid; i < ncb * 128; i += THREADS) {
        int c = i >> 7, col = i & 127;
        const float* er = embed_table + (long)embed_ids[c] * 16;
        float s = b0[col];
        #pragma unroll
        for (int k = 0; k < 16; k++) s += __ldg(er + k) * W0[k * 128 + col];
        EBIAS[c * 128 + col] = s;
    }

    // BF0: layer0 (inputs = feat32|sh16 -> W0 rows 16..63), KS=3
    for (int i = tid; i < 16 * 3 * 32; i += THREADS) {
        int lane = i & 31, js = i >> 5, s = js % 3, j = js / 3;
        int n = j * 8 + (lane >> 2), k0 = s * 16 + 2 * (lane & 3);
        uint16_t h[4], l[4];
        #pragma unroll
        for (int q = 0; q < 4; q++) {
            int k = k0 + (q >> 1) * 8 + (q & 1);
            split_rn(W0[(16 + k) * 128 + n], h[q], l[q]);
        }
        uint4 v;
        v.x = (uint32_t)h[0] | ((uint32_t)h[1] << 16);
        v.y = (uint32_t)h[2] | ((uint32_t)h[3] << 16);
        v.z = (uint32_t)l[0] | ((uint32_t)l[1] << 16);
        v.w = (uint32_t)l[2] | ((uint32_t)l[3] << 16);
        BF0[i] = v;
    }
    // BF1: layer1, KS=8
    for (int i = tid; i < 16 * 8 * 32; i += THREADS) {
        int lane = i & 31, js = i >> 5, s = js & 7, j = js >> 3;
        int n = j * 8 + (lane >> 2), k0 = s * 16 + 2 * (lane & 3);
        uint16_t h[4], l[4];
        #pragma unroll
        for (int q = 0; q < 4; q++) {
            int k = k0 + (q >> 1) * 8 + (q & 1);
            split_rn(W1[k * 128 + n], h[q], l[q]);
        }
        uint4 v;
        v.x = (uint32_t)h[0] | ((uint32_t)h[1] << 16);
        v.y = (uint32_t)h[2] | ((uint32_t)h[3] << 16);
        v.z = (uint32_t)l[0] | ((uint32_t)l[1] << 16);
        v.w = (uint32_t)l[2] | ((uint32_t)l[3] << 16);
        BF1[i] = v;
    }
    // BF2: layer2 (n padded to 8), KS=8
    for (int i = tid; i < 8 * 32; i += THREADS) {
        int lane = i & 31, s = i >> 5;
        int n = lane >> 2, k0 = s * 16 + 2 * (lane & 3);
        uint16_t h[4], l[4];
        #pragma unroll
        for (int q = 0; q < 4; q++) {
            int k = k0 + (q >> 1) * 8 + (q & 1);
            float w = (n < 3) ? W2[k * 3 + n] : 0.0f;
            split_rn(w, h[q], l[q]);
        }
        uint4 v;
        v.x = (uint32_t)h[0] | ((uint32_t)h[1] << 16);
        v.y = (uint32_t)h[2] | ((uint32_t)h[3] << 16);
        v.z = (uint32_t)l[0] | ((uint32_t)l[1] << 16);
        v.w = (uint32_t)l[2] | ((uint32_t)l[3] << 16);
        BF2[i] = v;
    }

    int deg = 3;
    if (sh_degree_p) deg = *sh_degree_p;
    const int nb_use = (deg + 1) * (deg + 1);
    __syncthreads();

    const int warp   = tid >> 5;
    const int lane   = tid & 31;
    const int pairid = warp >> 1;
    const int hw     = warp & 1;          // column half: cols [hw*64, hw*64+64)
    const int barid  = pairid + 1;        // named barriers 1..6

    // h buffers; x overlays the same region with its own stride
    uint32_t* hh = sm + U_HBUF + pairid * (2 * 32 * RS_H);
    uint32_t* hl = hh + 32 * RS_H;
    uint32_t* xh = hh;
    uint32_t* xl = hl;

    const int total  = C * N;
    const int ntiles = (total + TILE_PTS - 1) / TILE_PTS;

    const int r  = lane >> 2;
    const int cb = lane & 3;

    for (int tile = blockIdx.x * PAIRS + pairid; tile < ntiles; tile += gridDim.x * PAIRS) {
        const int tb = tile * TILE_PTS;

        // -------- x-build: warp builds its 16 rows; lane = (row, half) --------
        {
            const int row  = hw * 16 + (lane >> 1);
            const int half = lane & 1;
            const int p = tb + row;
            float v[24];
            if (p < total) {
                const int c = p / N;
                const int n = p - c * N;
                const float4* fr = (const float4*)(features + (long)n * 32);
                if (half == 0) {
                    #pragma unroll
                    for (int q = 0; q < 6; q++) {
                        float4 f = __ldg(fr + q);
                        v[4*q+0]=f.x; v[4*q+1]=f.y; v[4*q+2]=f.z; v[4*q+3]=f.w;
                    }
                } else {
                    #pragma unroll
                    for (int q = 0; q < 2; q++) {
                        float4 f = __ldg(fr + 6 + q);
                        v[4*q+0]=f.x; v[4*q+1]=f.y; v[4*q+2]=f.z; v[4*q+3]=f.w;
                    }
                    const float dx = dirs[(long)p*3 + 0];
                    const float dy = dirs[(long)p*3 + 1];
                    const float dz = dirs[(long)p*3 + 2];
                    float nrm = sqrtf(dx*dx + dy*dy + dz*dz);
                    float inv = 1.0f / fmaxf(nrm, 1e-12f);
                    const float sx = dx*inv, sy = dy*inv, sz = dz*inv;
                    const float z2     = sz * sz;
                    const float fTmp0B = -1.092548430592079f * sz;
                    const float fC1    = sx*sx - sy*sy;
                    const float fS1    = 2.0f * sx * sy;
                    const float fTmp0C = -2.285228997322329f * z2 + 0.4570457994644658f;
                    const float fTmp1B = 1.445305721320277f * sz;
                    const float fC2    = sx*fC1 - sy*fS1;
                    const float fS2    = sx*fS1 + sy*fC1;
                    float sh[16];
                    sh[0]  = 0.2820947917738781f;
                    sh[1]  = -0.48860251190292f * sy;
                    sh[2]  =  0.48860251190292f * sz;
                    sh[3]  = -0.48860251190292f * sx;
                    sh[4]  =  0.5462742152960395f * fS1;
                    sh[5]  =  fTmp0B * sy;
                    sh[6]  =  0.9461746957575601f * z2 - 0.3153915652525201f;
                    sh[7]  =  fTmp0B * sx;
                    sh[8]  =  0.5462742152960395f * fC1;
                    sh[9]  = -0.5900435899266435f * fS2;
                    sh[10] =  fTmp1B * fS1;
                    sh[11] =  fTmp0C * sy;
                    sh[12] =  sz * (1.865881662950577f * z2 - 1.119528997770346f);
                    sh[13] =  fTmp0C * sx;
                    sh[14] =  fTmp1B * fC1;
                    sh[15] = -0.5900435899266435f * fC2;
                    #pragma unroll
                    for (int k = 0; k < 16; k++) v[8 + k] = (k < nb_use) ? sh[k] : 0.0f;
                }
            } else {
                #pragma unroll
                for (int k = 0; k < 24; k++) v[k] = 0.0f;
            }
            const int wbase = row * RS_X + half * 12;
            #pragma unroll
            for (int w = 0; w < 12; w++) {
                float a = v[2*w], b = v[2*w+1];
                uint32_t ua = __float_as_uint(a), ub = __float_as_uint(b);
                xh[wbase + w] = __byte_perm(ua, ub, 0x7632);
                float la = a - __uint_as_float(ua & 0xFFFF0000u);
                float lb = b - __uint_as_float(ub & 0xFFFF0000u);
                xl[wbase + w] = pack_rn_bf16x2(la, lb);
            }
        }
        bar_pair(barid);                         // B1: x visible

        float Cacc[64];

        // -------- layer 0: 48 -> 128 --------
        layer_mma32<8, 3, RS_X>(Cacc, xh, xl, BF0, lane, hw * 8);
        bar_pair(barid);                         // B2: pair done reading x (h overlays x)

        // act_store with per-camera fused bias
        {
            int pA0 = tb + r;
            int cA0 = pA0 < total ? pA0 / N : 0;
            int cB0 = (pA0 + 8)  < total ? (pA0 + 8)  / N : 0;
            int cA1 = (pA0 + 16) < total ? (pA0 + 16) / N : 0;
            int cB1 = (pA0 + 24) < total ? (pA0 + 24) / N : 0;
            const float* eA0 = EBIAS + cA0 * 128;
            const float* eB0 = EBIAS + cB0 * 128;
            const float* eA1 = EBIAS + cA1 * 128;
            const float* eB1 = EBIAS + cB1 * 128;
            #pragma unroll
            for (int j = 0; j < 8; j++) {
                const int col = (hw * 8 + j) * 8 + 2 * cb;
                const int w   = (hw * 8 + j) * 4 + cb;
                float2 bA0 = *(const float2*)(eA0 + col);
                float2 bB0 = *(const float2*)(eB0 + col);
                store_frag(Cacc + j * 4, bA0.x, bA0.y, bB0.x, bB0.y, hh, hl, r, w, RS_H);
                float2 bA1 = *(const float2*)(eA1 + col);
                float2 bB1 = *(const float2*)(eB1 + col);
                store_frag(Cacc + 32 + j * 4, bA1.x, bA1.y, bB1.x, bB1.y, hh, hl, 16 + r, w, RS_H);
            }
        }
        bar_pair(barid);                         // B3: h0 visible

        // -------- layer 1: 128 -> 128 --------
        layer_mma32<8, 8, RS_H>(Cacc, hh, hl, BF1, lane, hw * 8);
        bar_pair(barid);                         // B4: pair done reading h0
        {
            #pragma unroll
            for (int j = 0; j < 8; j++) {
                const int col = (hw * 8 + j) * 8 + 2 * cb;
                const int w   = (hw * 8 + j) * 4 + cb;
                float2 bb = *(const float2*)(BIAS1 + col);
                store_frag(Cacc + j * 4,      bb.x, bb.y, bb.x, bb.y, hh, hl, r, w, RS_H);
                store_frag(Cacc + 32 + j * 4, bb.x, bb.y, bb.x, bb.y, hh, hl, 16 + r, w, RS_H);
            }
        }
        bar_pair(barid);                         // B5: h1 visible

        // -------- layer 2: 128 -> 3 (n pad 8); warp handles its 16 rows --------
        {
            float C2[4] = {0.f, 0.f, 0.f, 0.f};
            const int rb = hw * 16;
            #pragma unroll
            for (int s = 0; s < 8; s++) {
                const int cw = s * 8 + cb;
                uint32_t AH[4], AL[4];
                load_afrag(AH, hh, rb, r, cw, RS_H);
                load_afrag(AL, hl, rb, r, cw, RS_H);
                uint4 b = BF2[s * 32 + lane];
                mma_bf16(C2, AH, b.x, b.y);
                mma_bf16(C2, AH, b.z, b.w);
                mma_bf16(C2, AL, b.x, b.y);
            }
            const int p0 = tb + rb + r;
            const int p1 = p0 + 8;
            if (cb == 0) {
                if (p0 < total) {
                    out[(long)p0*3 + 0] = C2[0] + BIAS2[0];
                    out[(long)p0*3 + 1] = C2[1] + BIAS2[1];
                }
                if (p1 < total) {
                    out[(long)p1*3 + 0] = C2[2] + BIAS2[0];
                    out[(long)p1*3 + 1] = C2[3] + BIAS2[1];
                }
            } else if (cb == 1) {
                if (p0 < total) out[(long)p0*3 + 2] = C2[0] + BIAS2[2];
                if (p1 < total) out[(long)p1*3 + 2] = C2[2] + BIAS2[2];
            }
        }
        bar_pair(barid);                         // B6: pair done with h1 (next x overlays)
    }
}

extern "C" void kernel_launch(void* const* d_in, const int* in_sizes, int n_in,
                              void* d_out, int out_size)
{
    const float* features    = (const float*)d_in[0];
    const float* dirs        = (const float*)d_in[1];
    const float* embed_table = (const float*)d_in[2];
    const float* W0          = (const float*)d_in[3];
    const float* b0          = (const float*)d_in[4];
    const float* W1          = (const float*)d_in[5];
    const float* b1          = (const float*)d_in[6];
    const float* W2          = (const float*)d_in[7];
    const float* b2          = (const float*)d_in[8];
    const int*   embed_ids   = (const int*)d_in[9];
    const int*   sh_degree_p = (n_in > 10) ? (const int*)d_in[10] : nullptr;
    float* out = (float*)d_out;

    const int C = in_sizes[9];
    const int N = in_sizes[1] / (3 * C);
    const int total = C * N;
    const int ntiles = (total + TILE_PTS - 1) / TILE_PTS;
    const int cta_tiles = (ntiles + PAIRS - 1) / PAIRS;

    int dev = 0, sms = 148;
    cudaGetDevice(&dev);
    cudaDeviceGetAttribute(&sms, cudaDevAttrMultiProcessorCount, dev);
    int grid = sms < cta_tiles ? sms : cta_tiles;

    const size_t smem_bytes = (size_t)U_TOTAL * 4;
    cudaFuncSetAttribute(vdc_mlp_mma384_kernel,
                         cudaFuncAttributeMaxDynamicSharedMemorySize, (int)smem_bytes);

    vdc_mlp_mma384_kernel<<<grid, THREADS, smem_bytes>>>(
        features, dirs, embed_table, W0, b0, W1, b1, W2, b2,
        embed_ids, sh_degree_p, out, C, N);
}

// round 7
// speedup vs baseline: 4.5960x; 1.1414x over previous
#include <cuda_runtime.h>
#include <cuda_bf16.h>
#include <cstdint>

#define THREADS 256
#define NW      8             // warps per CTA, each fully independent
#define TILE    16            // points per warp tile
#define RS_X    28            // x-stage row stride (u32 words)

// ---- smem layout (u32 units) ----
#define U_EBIAS  0                         // 8 cams x 128 floats (b0 + emb@W0[0:16])
#define U_BIAS1  1024                      // 128
#define U_BIAS2  1152                      // 8
#define U_BF0    1160                      // 16j*3s*32 uint4 = 6144 u32
#define U_BF1    (U_BF0 + 6144)            // 16j*8s*32 uint4 = 16384 u32
#define U_BF2    (U_BF1 + 16384)           // 8s*32 uint4 = 1024 u32
#define U_XBUF   (U_BF2 + 1024)            // 8 warps * 16*RS_X*2
#define U_TOTAL  (U_XBUF + NW*16*RS_X*2)   // 31880 u32 = 127520 B

__device__ __forceinline__ void mma_bf16(float c[4], const uint32_t a[4],
                                         uint32_t b0, uint32_t b1) {
    asm("mma.sync.aligned.m16n8k16.row.col.f32.bf16.bf16.f32 "
        "{%0,%1,%2,%3}, {%4,%5,%6,%7}, {%8,%9}, {%0,%1,%2,%3};"
        : "+f"(c[0]), "+f"(c[1]), "+f"(c[2]), "+f"(c[3])
        : "r"(a[0]), "r"(a[1]), "r"(a[2]), "r"(a[3]), "r"(b0), "r"(b1));
}
__device__ __forceinline__ uint32_t pack_rn_bf16x2(float lo_elem, float hi_elem) {
    uint32_t r;
    asm("cvt.rn.bf16x2.f32 %0, %1, %2;" : "=r"(r) : "f"(hi_elem), "f"(lo_elem));
    return r;
}
__device__ __forceinline__ void split_rn(float v, uint16_t& h, uint16_t& l) {
    __nv_bfloat16 bh = __float2bfloat16(v);
    float res = v - __bfloat162float(bh);
    __nv_bfloat16 bl = __float2bfloat16(res);
    h = __bfloat16_as_ushort(bh);
    l = __bfloat16_as_ushort(bl);
}

// relu(acc+bias) for 4-frag, split into hi (trunc) / lo (rn residual) bf16x2 regs
__device__ __forceinline__ void cvt_frag(const float* c, float bxA, float byA,
                                         float bxB, float byB,
                                         uint32_t& h01, uint32_t& h23,
                                         uint32_t& l01, uint32_t& l23) {
    float v0 = fmaxf(c[0] + bxA, 0.0f), v1 = fmaxf(c[1] + byA, 0.0f);
    float v2 = fmaxf(c[2] + bxB, 0.0f), v3 = fmaxf(c[3] + byB, 0.0f);
    uint32_t u0 = __float_as_uint(v0), u1 = __float_as_uint(v1);
    uint32_t u2 = __float_as_uint(v2), u3 = __float_as_uint(v3);
    h01 = __byte_perm(u0, u1, 0x7632);
    h23 = __byte_perm(u2, u3, 0x7632);
    float l0 = v0 - __uint_as_float(u0 & 0xFFFF0000u);
    float l1 = v1 - __uint_as_float(u1 & 0xFFFF0000u);
    float l2 = v2 - __uint_as_float(u2 & 0xFFFF0000u);
    float l3 = v3 - __uint_as_float(u3 & 0xFFFF0000u);
    l01 = pack_rn_bf16x2(l0, l1);
    l23 = pack_rn_bf16x2(l2, l3);
}

__global__ void __launch_bounds__(THREADS, 1) vdc_mlp_regpipe_kernel(
    const float* __restrict__ features,     // [N, 32]
    const float* __restrict__ dirs,         // [C, N, 3]
    const float* __restrict__ embed_table,  // [1000, 16]
    const float* __restrict__ W0,           // [64, 128]
    const float* __restrict__ b0,
    const float* __restrict__ W1,           // [128, 128]
    const float* __restrict__ b1,
    const float* __restrict__ W2,           // [128, 3]
    const float* __restrict__ b2,
    const int*   __restrict__ embed_ids,    // [C]
    const int*   __restrict__ sh_degree_p,
    float*       __restrict__ out,          // [C, N, 3]
    int C, int N)
{
    extern __shared__ uint32_t sm[];
    float* EBIAS = (float*)(sm + U_EBIAS);   // [8][128]
    float* BIAS1 = (float*)(sm + U_BIAS1);
    float* BIAS2 = (float*)(sm + U_BIAS2);
    const uint4* BF0 = (const uint4*)(sm + U_BF0);
    const uint4* BF1 = (const uint4*)(sm + U_BF1);
    const uint4* BF2 = (const uint4*)(sm + U_BF2);

    const int tid = threadIdx.x;

    // ---------------- one-time staging ----------------
    for (int i = tid; i < 128; i += THREADS) BIAS1[i] = b1[i];
    if (tid < 8) BIAS2[tid] = (tid < 3) ? b2[tid] : 0.0f;

    // per-camera fused bias: ebias[c] = b0 + emb_c @ W0[0:16,:]
    const int ncb = (C < 8 ? C : 8);
    for (int i = tid; i < ncb * 128; i += THREADS) {
        int c = i >> 7, col = i & 127;
        const float* er = embed_table + (long)embed_ids[c] * 16;
        float s = b0[col];
        #pragma unroll
        for (int k = 0; k < 16; k++) s += __ldg(er + k) * W0[k * 128 + col];
        EBIAS[c * 128 + col] = s;
    }

    // BF0: layer0 B frags (inputs = feat32|sh16 -> W0 rows 16..63), KS=3, j 0..15
    for (int i = tid; i < 16 * 3 * 32; i += THREADS) {
        int lane = i & 31, js = i >> 5, s = js % 3, j = js / 3;
        int n = j * 8 + (lane >> 2), k0 = s * 16 + 2 * (lane & 3);
        uint16_t h[4], l[4];
        #pragma unroll
        for (int q = 0; q < 4; q++) {
            int k = k0 + (q >> 1) * 8 + (q & 1);
            split_rn(W0[(16 + k) * 128 + n], h[q], l[q]);
        }
        uint4 v;
        v.x = (uint32_t)h[0] | ((uint32_t)h[1] << 16);
        v.y = (uint32_t)h[2] | ((uint32_t)h[3] << 16);
        v.z = (uint32_t)l[0] | ((uint32_t)l[1] << 16);
        v.w = (uint32_t)l[2] | ((uint32_t)l[3] << 16);
        ((uint4*)(sm + U_BF0))[i] = v;
    }
    // BF1: layer1, KS=8, j 0..15
    for (int i = tid; i < 16 * 8 * 32; i += THREADS) {
        int lane = i & 31, js = i >> 5, s = js & 7, j = js >> 3;
        int n = j * 8 + (lane >> 2), k0 = s * 16 + 2 * (lane & 3);
        uint16_t h[4], l[4];
        #pragma unroll
        for (int q = 0; q < 4; q++) {
            int k = k0 + (q >> 1) * 8 + (q & 1);
            split_rn(W1[k * 128 + n], h[q], l[q]);
        }
        uint4 v;
        v.x = (uint32_t)h[0] | ((uint32_t)h[1] << 16);
        v.y = (uint32_t)h[2] | ((uint32_t)h[3] << 16);
        v.z = (uint32_t)l[0] | ((uint32_t)l[1] << 16);
        v.w = (uint32_t)l[2] | ((uint32_t)l[3] << 16);
        ((uint4*)(sm + U_BF1))[i] = v;
    }
    // BF2: layer2 (n padded to 8), KS=8
    for (int i = tid; i < 8 * 32; i += THREADS) {
        int lane = i & 31, s = i >> 5;
        int n = lane >> 2, k0 = s * 16 + 2 * (lane & 3);
        uint16_t h[4], l[4];
        #pragma unroll
        for (int q = 0; q < 4; q++) {
            int k = k0 + (q >> 1) * 8 + (q & 1);
            float w = (n < 3) ? W2[k * 3 + n] : 0.0f;
            split_rn(w, h[q], l[q]);
        }
        uint4 v;
        v.x = (uint32_t)h[0] | ((uint32_t)h[1] << 16);
        v.y = (uint32_t)h[2] | ((uint32_t)h[3] << 16);
        v.z = (uint32_t)l[0] | ((uint32_t)l[1] << 16);
        v.w = (uint32_t)l[2] | ((uint32_t)l[3] << 16);
        ((uint4*)(sm + U_BF2))[i] = v;
    }

    int deg = 3;
    if (sh_degree_p) deg = *sh_degree_p;
    const int nb_use = (deg + 1) * (deg + 1);
    __syncthreads();

    const int warp = tid >> 5;
    const int lane = tid & 31;
    const int r  = lane >> 2;
    const int cb = lane & 3;

    uint32_t* xh = sm + U_XBUF + warp * (2 * 16 * RS_X);
    uint32_t* xl = xh + 16 * RS_X;

    const int total  = C * N;
    const int ntiles = (total + TILE - 1) / TILE;

    for (int tile = blockIdx.x * NW + warp; tile < ntiles; tile += gridDim.x * NW) {
        const int tb = tile * TILE;
        __syncwarp();     // prior tile's x reads done before overwrite

        // -------- x-build: lane = (row = lane>>1, half = lane&1) --------
        {
            const int row  = lane >> 1;
            const int half = lane & 1;
            const int p = tb + row;
            float v[24];
            if (p < total) {
                const int c = p / N;
                const int n = p - c * N;
                const float4* fr = (const float4*)(features + (long)n * 32);
                if (half == 0) {
                    #pragma unroll
                    for (int q = 0; q < 6; q++) {
                        float4 f = __ldg(fr + q);
                        v[4*q+0]=f.x; v[4*q+1]=f.y; v[4*q+2]=f.z; v[4*q+3]=f.w;
                    }
                } else {
                    #pragma unroll
                    for (int q = 0; q < 2; q++) {
                        float4 f = __ldg(fr + 6 + q);
                        v[4*q+0]=f.x; v[4*q+1]=f.y; v[4*q+2]=f.z; v[4*q+3]=f.w;
                    }
                    const float dx = dirs[(long)p*3 + 0];
                    const float dy = dirs[(long)p*3 + 1];
                    const float dz = dirs[(long)p*3 + 2];
                    float nrm = sqrtf(dx*dx + dy*dy + dz*dz);
                    float inv = 1.0f / fmaxf(nrm, 1e-12f);
                    const float sx = dx*inv, sy = dy*inv, sz = dz*inv;
                    const float z2     = sz * sz;
                    const float fTmp0B = -1.092548430592079f * sz;
                    const float fC1    = sx*sx - sy*sy;
                    const float fS1    = 2.0f * sx * sy;
                    const float fTmp0C = -2.285228997322329f * z2 + 0.4570457994644658f;
                    const float fTmp1B = 1.445305721320277f * sz;
                    const float fC2    = sx*fC1 - sy*fS1;
                    const float fS2    = sx*fS1 + sy*fC1;
                    float sh[16];
                    sh[0]  = 0.2820947917738781f;
                    sh[1]  = -0.48860251190292f * sy;
                    sh[2]  =  0.48860251190292f * sz;
                    sh[3]  = -0.48860251190292f * sx;
                    sh[4]  =  0.5462742152960395f * fS1;
                    sh[5]  =  fTmp0B * sy;
                    sh[6]  =  0.9461746957575601f * z2 - 0.3153915652525201f;
                    sh[7]  =  fTmp0B * sx;
                    sh[8]  =  0.5462742152960395f * fC1;
                    sh[9]  = -0.5900435899266435f * fS2;
                    sh[10] =  fTmp1B * fS1;
                    sh[11] =  fTmp0C * sy;
                    sh[12] =  sz * (1.865881662950577f * z2 - 1.119528997770346f);
                    sh[13] =  fTmp0C * sx;
                    sh[14] =  fTmp1B * fC1;
                    sh[15] = -0.5900435899266435f * fC2;
                    #pragma unroll
                    for (int k = 0; k < 16; k++) v[8 + k] = (k < nb_use) ? sh[k] : 0.0f;
                }
            } else {
                #pragma unroll
                for (int k = 0; k < 24; k++) v[k] = 0.0f;
            }
            const int wbase = (lane >> 1) * RS_X + half * 12;
            #pragma unroll
            for (int w = 0; w < 12; w++) {
                float a = v[2*w], b = v[2*w+1];
                uint32_t ua = __float_as_uint(a), ub = __float_as_uint(b);
                xh[wbase + w] = __byte_perm(ua, ub, 0x7632);
                float la = a - __uint_as_float(ua & 0xFFFF0000u);
                float lb = b - __uint_as_float(ub & 0xFFFF0000u);
                xl[wbase + w] = pack_rn_bf16x2(la, lb);
            }
        }
        __syncwarp();

        // -------- layer 0: 48 -> 128 (A from smem x-buf) --------
        float acc[64];
        #pragma unroll
        for (int i = 0; i < 64; i++) acc[i] = 0.0f;
        #pragma unroll
        for (int s = 0; s < 3; s++) {
            const int cw = s * 8 + cb;
            uint32_t AH[4], AL[4];
            AH[0] = xh[r * RS_X + cw];       AH[1] = xh[(r + 8) * RS_X + cw];
            AH[2] = xh[r * RS_X + cw + 4];   AH[3] = xh[(r + 8) * RS_X + cw + 4];
            AL[0] = xl[r * RS_X + cw];       AL[1] = xl[(r + 8) * RS_X + cw];
            AL[2] = xl[r * RS_X + cw + 4];   AL[3] = xl[(r + 8) * RS_X + cw + 4];
            #pragma unroll
            for (int j = 0; j < 16; j++) {
                uint4 b = BF0[(j * 3 + s) * 32 + lane];
                float* c = acc + j * 4;
                mma_bf16(c, AH, b.x, b.y);
                mma_bf16(c, AH, b.z, b.w);
                mma_bf16(c, AL, b.x, b.y);
            }
        }

        // -------- epilogue 0: relu(acc + ebias) -> A1 frags (registers) --------
        uint32_t A1H[32], A1L[32];
        {
            const int pA = tb + r, pB = tb + r + 8;
            const int cA = (pA < total) ? pA / N : 0;
            const int cB = (pB < total) ? pB / N : 0;
            const float* eA = EBIAS + cA * 128;
            const float* eB = EBIAS + cB * 128;
            #pragma unroll
            for (int j = 0; j < 16; j++) {
                float2 bA = *(const float2*)(eA + j * 8 + 2 * cb);
                float2 bB = *(const float2*)(eB + j * 8 + 2 * cb);
                const int idx = (j >> 1) * 4 + (j & 1) * 2;
                cvt_frag(acc + j * 4, bA.x, bA.y, bB.x, bB.y,
                         A1H[idx], A1H[idx + 1], A1L[idx], A1L[idx + 1]);
            }
        }

        // -------- layer 1: 128 -> 128 (A from registers) --------
        float acc1[64];
        #pragma unroll
        for (int i = 0; i < 64; i++) acc1[i] = 0.0f;
        #pragma unroll
        for (int s = 0; s < 8; s++) {
            #pragma unroll
            for (int j = 0; j < 16; j++) {
                uint4 b = BF1[(j * 8 + s) * 32 + lane];
                float* c = acc1 + j * 4;
                mma_bf16(c, A1H + s * 4, b.x, b.y);
                mma_bf16(c, A1H + s * 4, b.z, b.w);
                mma_bf16(c, A1L + s * 4, b.x, b.y);
            }
        }

        // -------- epilogue 1: relu(acc1 + b1) -> A2 frags (reuse A1 regs) --------
        #pragma unroll
        for (int j = 0; j < 16; j++) {
            float2 bb = *(const float2*)(BIAS1 + j * 8 + 2 * cb);
            const int idx = (j >> 1) * 4 + (j & 1) * 2;
            cvt_frag(acc1 + j * 4, bb.x, bb.y, bb.x, bb.y,
                     A1H[idx], A1H[idx + 1], A1L[idx], A1L[idx + 1]);
        }

        // -------- layer 2: 128 -> 3 (n padded to 8) --------
        float C2[4] = {0.f, 0.f, 0.f, 0.f};
        #pragma unroll
        for (int s = 0; s < 8; s++) {
            uint4 b = BF2[s * 32 + lane];
            mma_bf16(C2, A1H + s * 4, b.x, b.y);
            mma_bf16(C2, A1H + s * 4, b.z, b.w);
            mma_bf16(C2, A1L + s * 4, b.x, b.y);
        }

        // -------- output --------
        {
            const int p0 = tb + r;
            const int p1 = p0 + 8;
            if (cb == 0) {
                if (p0 < total) {
                    out[(long)p0*3 + 0] = C2[0] + BIAS2[0];
                    out[(long)p0*3 + 1] = C2[1] + BIAS2[1];
                }
                if (p1 < total) {
                    out[(long)p1*3 + 0] = C2[2] + BIAS2[0];
                    out[(long)p1*3 + 1] = C2[3] + BIAS2[1];
                }
            } else if (cb == 1) {
                if (p0 < total) out[(long)p0*3 + 2] = C2[0] + BIAS2[2];
                if (p1 < total) out[(long)p1*3 + 2] = C2[2] + BIAS2[2];
            }
        }
    }
}

extern "C" void kernel_launch(void* const* d_in, const int* in_sizes, int n_in,
                              void* d_out, int out_size)
{
    const float* features    = (const float*)d_in[0];
    const float* dirs        = (const float*)d_in[1];
    const float* embed_table = (const float*)d_in[2];
    const float* W0          = (const float*)d_in[3];
    const float* b0          = (const float*)d_in[4];
    const float* W1          = (const float*)d_in[5];
    const float* b1          = (const float*)d_in[6];
    const float* W2          = (const float*)d_in[7];
    const float* b2          = (const float*)d_in[8];
    const int*   embed_ids   = (const int*)d_in[9];
    const int*   sh_degree_p = (n_in > 10) ? (const int*)d_in[10] : nullptr;
    float* out = (float*)d_out;

    const int C = in_sizes[9];
    const int N = in_sizes[1] / (3 * C);
    const int total = C * N;
    const int ntiles = (total + TILE - 1) / TILE;
    const int cta_tiles = (ntiles + NW - 1) / NW;

    int dev = 0, sms = 148;
    cudaGetDevice(&dev);
    cudaDeviceGetAttribute(&sms, cudaDevAttrMultiProcessorCount, dev);
    int grid = sms < cta_tiles ? sms : cta_tiles;

    const size_t smem_bytes = (size_t)U_TOTAL * 4;
    cudaFuncSetAttribute(vdc_mlp_regpipe_kernel,
                         cudaFuncAttributeMaxDynamicSharedMemorySize, (int)smem_bytes);

    vdc_mlp_regpipe_kernel<<<grid, THREADS, smem_bytes>>>(
        features, dirs, embed_table, W0, b0, W1, b1, W2, b2,
        embed_ids, sh_degree_p, out, C, N);
}

// round 8
// speedup vs baseline: 4.7356x; 1.0304x over previous
#include <cuda_runtime.h>
#include <cuda_bf16.h>
#include <cstdint>

#define THREADS 384
#define NW      12            // warps per CTA, each fully independent
#define TILE    16            // points per warp tile
#define RS_X    28            // x-stage row stride (u32 words)

// ---- smem layout (u32 units) ----
#define U_EBIAS  0                         // 8 cams x 128 floats (b0 + emb@W0[0:16])
#define U_BIAS1  1024                      // 128
#define U_BIAS2  1152                      // 8
#define U_BF0    1160                      // 16j*3s*32 uint4 = 6144 u32
#define U_BF1    (U_BF0 + 6144)            // 16j*8s*32 uint4 = 16384 u32
#define U_BF2    (U_BF1 + 16384)           // 8s*32 uint4 = 1024 u32
#define U_XBUF   (U_BF2 + 1024)            // 12 warps * 16*RS_X*2
#define U_TOTAL  (U_XBUF + NW*16*RS_X*2)   // 35464 u32 = 141856 B

__device__ __forceinline__ void mma_bf16(float c[4], const uint32_t a[4],
                                         uint32_t b0, uint32_t b1) {
    asm("mma.sync.aligned.m16n8k16.row.col.f32.bf16.bf16.f32 "
        "{%0,%1,%2,%3}, {%4,%5,%6,%7}, {%8,%9}, {%0,%1,%2,%3};"
        : "+f"(c[0]), "+f"(c[1]), "+f"(c[2]), "+f"(c[3])
        : "r"(a[0]), "r"(a[1]), "r"(a[2]), "r"(a[3]), "r"(b0), "r"(b1));
}
__device__ __forceinline__ uint32_t pack_rn_bf16x2(float lo_elem, float hi_elem) {
    uint32_t r;
    asm("cvt.rn.bf16x2.f32 %0, %1, %2;" : "=r"(r) : "f"(hi_elem), "f"(lo_elem));
    return r;
}
__device__ __forceinline__ void split_rn(float v, uint16_t& h, uint16_t& l) {
    __nv_bfloat16 bh = __float2bfloat16(v);
    float res = v - __bfloat162float(bh);
    __nv_bfloat16 bl = __float2bfloat16(res);
    h = __bfloat16_as_ushort(bh);
    l = __bfloat16_as_ushort(bl);
}

// relu(acc+bias) for 4-frag, split into hi (trunc) / lo (rn residual) bf16x2 regs
__device__ __forceinline__ void cvt_frag(const float* c, float bxA, float byA,
                                         float bxB, float byB,
                                         uint32_t& h01, uint32_t& h23,
                                         uint32_t& l01, uint32_t& l23) {
    float v0 = fmaxf(c[0] + bxA, 0.0f), v1 = fmaxf(c[1] + byA, 0.0f);
    float v2 = fmaxf(c[2] + bxB, 0.0f), v3 = fmaxf(c[3] + byB, 0.0f);
    uint32_t u0 = __float_as_uint(v0), u1 = __float_as_uint(v1);
    uint32_t u2 = __float_as_uint(v2), u3 = __float_as_uint(v3);
    h01 = __byte_perm(u0, u1, 0x7632);
    h23 = __byte_perm(u2, u3, 0x7632);
    float l0 = v0 - __uint_as_float(u0 & 0xFFFF0000u);
    float l1 = v1 - __uint_as_float(u1 & 0xFFFF0000u);
    float l2 = v2 - __uint_as_float(u2 & 0xFFFF0000u);
    float l3 = v3 - __uint_as_float(u3 & 0xFFFF0000u);
    l01 = pack_rn_bf16x2(l0, l1);
    l23 = pack_rn_bf16x2(l2, l3);
}

__global__ void __launch_bounds__(THREADS, 1) vdc_mlp_regpipe12_kernel(
    const float* __restrict__ features,     // [N, 32]
    const float* __restrict__ dirs,         // [C, N, 3]
    const float* __restrict__ embed_table,  // [1000, 16]
    const float* __restrict__ W0,           // [64, 128]
    const float* __restrict__ b0,
    const float* __restrict__ W1,           // [128, 128]
    const float* __restrict__ b1,
    const float* __restrict__ W2,           // [128, 3]
    const float* __restrict__ b2,
    const int*   __restrict__ embed_ids,    // [C]
    const int*   __restrict__ sh_degree_p,
    float*       __restrict__ out,          // [C, N, 3]
    int C, int N)
{
    extern __shared__ uint32_t sm[];
    float* EBIAS = (float*)(sm + U_EBIAS);   // [8][128]
    float* BIAS1 = (float*)(sm + U_BIAS1);
    float* BIAS2 = (float*)(sm + U_BIAS2);
    const uint4* BF0 = (const uint4*)(sm + U_BF0);
    const uint4* BF1 = (const uint4*)(sm + U_BF1);
    const uint4* BF2 = (const uint4*)(sm + U_BF2);

    const int tid = threadIdx.x;

    // ---------------- one-time staging ----------------
    for (int i = tid; i < 128; i += THREADS) BIAS1[i] = b1[i];
    if (tid < 8) BIAS2[tid] = (tid < 3) ? b2[tid] : 0.0f;

    const int ncb = (C < 8 ? C : 8);
    for (int i = tid; i < ncb * 128; i += THREADS) {
        int c = i >> 7, col = i & 127;
        const float* er = embed_table + (long)embed_ids[c] * 16;
        float s = b0[col];
        #pragma unroll
        for (int k = 0; k < 16; k++) s += __ldg(er + k) * W0[k * 128 + col];
        EBIAS[c * 128 + col] = s;
    }

    // BF0: layer0 B frags (inputs = feat32|sh16 -> W0 rows 16..63), KS=3, j 0..15
    for (int i = tid; i < 16 * 3 * 32; i += THREADS) {
        int lane = i & 31, js = i >> 5, s = js % 3, j = js / 3;
        int n = j * 8 + (lane >> 2), k0 = s * 16 + 2 * (lane & 3);
        uint16_t h[4], l[4];
        #pragma unroll
        for (int q = 0; q < 4; q++) {
            int k = k0 + (q >> 1) * 8 + (q & 1);
            split_rn(W0[(16 + k) * 128 + n], h[q], l[q]);
        }
        uint4 v;
        v.x = (uint32_t)h[0] | ((uint32_t)h[1] << 16);
        v.y = (uint32_t)h[2] | ((uint32_t)h[3] << 16);
        v.z = (uint32_t)l[0] | ((uint32_t)l[1] << 16);
        v.w = (uint32_t)l[2] | ((uint32_t)l[3] << 16);
        ((uint4*)(sm + U_BF0))[i] = v;
    }
    // BF1: layer1, KS=8, j 0..15
    for (int i = tid; i < 16 * 8 * 32; i += THREADS) {
        int lane = i & 31, js = i >> 5, s = js & 7, j = js >> 3;
        int n = j * 8 + (lane >> 2), k0 = s * 16 + 2 * (lane & 3);
        uint16_t h[4], l[4];
        #pragma unroll
        for (int q = 0; q < 4; q++) {
            int k = k0 + (q >> 1) * 8 + (q & 1);
            split_rn(W1[k * 128 + n], h[q], l[q]);
        }
        uint4 v;
        v.x = (uint32_t)h[0] | ((uint32_t)h[1] << 16);
        v.y = (uint32_t)h[2] | ((uint32_t)h[3] << 16);
        v.z = (uint32_t)l[0] | ((uint32_t)l[1] << 16);
        v.w = (uint32_t)l[2] | ((uint32_t)l[3] << 16);
        ((uint4*)(sm + U_BF1))[i] = v;
    }
    // BF2: layer2 (n padded to 8), KS=8
    for (int i = tid; i < 8 * 32; i += THREADS) {
        int lane = i & 31, s = i >> 5;
        int n = lane >> 2, k0 = s * 16 + 2 * (lane & 3);
        uint16_t h[4], l[4];
        #pragma unroll
        for (int q = 0; q < 4; q++) {
            int k = k0 + (q >> 1) * 8 + (q & 1);
            float w = (n < 3) ? W2[k * 3 + n] : 0.0f;
            split_rn(w, h[q], l[q]);
        }
        uint4 v;
        v.x = (uint32_t)h[0] | ((uint32_t)h[1] << 16);
        v.y = (uint32_t)h[2] | ((uint32_t)h[3] << 16);
        v.z = (uint32_t)l[0] | ((uint32_t)l[1] << 16);
        v.w = (uint32_t)l[2] | ((uint32_t)l[3] << 16);
        ((uint4*)(sm + U_BF2))[i] = v;
    }

    int deg = 3;
    if (sh_degree_p) deg = *sh_degree_p;
    const int nb_use = (deg + 1) * (deg + 1);
    __syncthreads();

    const int warp = tid >> 5;
    const int lane = tid & 31;
    const int r  = lane >> 2;
    const int cb = lane & 3;

    uint32_t* xh = sm + U_XBUF + warp * (2 * 16 * RS_X);
    uint32_t* xl = xh + 16 * RS_X;

    const int total  = C * N;
    const int ntiles = (total + TILE - 1) / TILE;

    for (int tile = blockIdx.x * NW + warp; tile < ntiles; tile += gridDim.x * NW) {
        const int tb = tile * TILE;
        __syncwarp();     // prior tile's x reads done before overwrite

        // -------- x-build: lane = (row = lane>>1, half = lane&1) --------
        {
            const int row  = lane >> 1;
            const int half = lane & 1;
            const int p = tb + row;
            float v[24];
            if (p < total) {
                const int c = p / N;
                const int n = p - c * N;
                const float4* fr = (const float4*)(features + (long)n * 32);
                if (half == 0) {
                    #pragma unroll
                    for (int q = 0; q < 6; q++) {
                        float4 f = __ldg(fr + q);
                        v[4*q+0]=f.x; v[4*q+1]=f.y; v[4*q+2]=f.z; v[4*q+3]=f.w;
                    }
                } else {
                    #pragma unroll
                    for (int q = 0; q < 2; q++) {
                        float4 f = __ldg(fr + 6 + q);
                        v[4*q+0]=f.x; v[4*q+1]=f.y; v[4*q+2]=f.z; v[4*q+3]=f.w;
                    }
                    const float dx = dirs[(long)p*3 + 0];
                    const float dy = dirs[(long)p*3 + 1];
                    const float dz = dirs[(long)p*3 + 2];
                    float nrm = sqrtf(dx*dx + dy*dy + dz*dz);
                    float inv = 1.0f / fmaxf(nrm, 1e-12f);
                    const float sx = dx*inv, sy = dy*inv, sz = dz*inv;
                    const float z2     = sz * sz;
                    const float fTmp0B = -1.092548430592079f * sz;
                    const float fC1    = sx*sx - sy*sy;
                    const float fS1    = 2.0f * sx * sy;
                    const float fTmp0C = -2.285228997322329f * z2 + 0.4570457994644658f;
                    const float fTmp1B = 1.445305721320277f * sz;
                    const float fC2    = sx*fC1 - sy*fS1;
                    const float fS2    = sx*fS1 + sy*fC1;
                    float sh[16];
                    sh[0]  = 0.2820947917738781f;
                    sh[1]  = -0.48860251190292f * sy;
                    sh[2]  =  0.48860251190292f * sz;
                    sh[3]  = -0.48860251190292f * sx;
                    sh[4]  =  0.5462742152960395f * fS1;
                    sh[5]  =  fTmp0B * sy;
                    sh[6]  =  0.9461746957575601f * z2 - 0.3153915652525201f;
                    sh[7]  =  fTmp0B * sx;
                    sh[8]  =  0.5462742152960395f * fC1;
                    sh[9]  = -0.5900435899266435f * fS2;
                    sh[10] =  fTmp1B * fS1;
                    sh[11] =  fTmp0C * sy;
                    sh[12] =  sz * (1.865881662950577f * z2 - 1.119528997770346f);
                    sh[13] =  fTmp0C * sx;
                    sh[14] =  fTmp1B * fC1;
                    sh[15] = -0.5900435899266435f * fC2;
                    #pragma unroll
                    for (int k = 0; k < 16; k++) v[8 + k] = (k < nb_use) ? sh[k] : 0.0f;
                }
            } else {
                #pragma unroll
                for (int k = 0; k < 24; k++) v[k] = 0.0f;
            }
            const int wbase = (lane >> 1) * RS_X + half * 12;
            #pragma unroll
            for (int w = 0; w < 12; w++) {
                float a = v[2*w], b = v[2*w+1];
                uint32_t ua = __float_as_uint(a), ub = __float_as_uint(b);
                xh[wbase + w] = __byte_perm(ua, ub, 0x7632);
                float la = a - __uint_as_float(ua & 0xFFFF0000u);
                float lb = b - __uint_as_float(ub & 0xFFFF0000u);
                xl[wbase + w] = pack_rn_bf16x2(la, lb);
            }
        }
        __syncwarp();

        // camera bias rows for this tile (cheap, reused in epilogue 0)
        const int pA = tb + r, pB = tb + r + 8;
        const float* eA = EBIAS + ((pA < total) ? (pA / N) : 0) * 128;
        const float* eB = EBIAS + ((pB < total) ? (pB / N) : 0) * 128;

        uint32_t A1H[32], A1L[32];     // layer-1 A fragments (built by epilogue 0)

        // -------- layer 0 (48 -> 128) in two j-halves of 8 col-tiles --------
        #pragma unroll
        for (int jh = 0; jh < 2; jh++) {
            float acc[32];
            #pragma unroll
            for (int i = 0; i < 32; i++) acc[i] = 0.0f;
            #pragma unroll
            for (int s = 0; s < 3; s++) {
                const int cw = s * 8 + cb;
                uint32_t AH[4], AL[4];
                AH[0] = xh[r * RS_X + cw];       AH[1] = xh[(r + 8) * RS_X + cw];
                AH[2] = xh[r * RS_X + cw + 4];   AH[3] = xh[(r + 8) * RS_X + cw + 4];
                AL[0] = xl[r * RS_X + cw];       AL[1] = xl[(r + 8) * RS_X + cw];
                AL[2] = xl[r * RS_X + cw + 4];   AL[3] = xl[(r + 8) * RS_X + cw + 4];
                #pragma unroll
                for (int jj = 0; jj < 8; jj++) {
                    const int j = jh * 8 + jj;
                    uint4 b = BF0[(j * 3 + s) * 32 + lane];
                    float* c = acc + jj * 4;
                    mma_bf16(c, AH, b.x, b.y);
                    mma_bf16(c, AH, b.z, b.w);
                    mma_bf16(c, AL, b.x, b.y);
                }
            }
            // epilogue 0 half: relu(acc + ebias) -> A1 frags for s = jh*4 .. jh*4+3
            #pragma unroll
            for (int jj = 0; jj < 8; jj++) {
                const int j = jh * 8 + jj;
                float2 bA = *(const float2*)(eA + j * 8 + 2 * cb);
                float2 bB = *(const float2*)(eB + j * 8 + 2 * cb);
                const int idx = (j >> 1) * 4 + (j & 1) * 2;
                cvt_frag(acc + jj * 4, bA.x, bA.y, bB.x, bB.y,
                         A1H[idx], A1H[idx + 1], A1L[idx], A1L[idx + 1]);
            }
        }

        // -------- layer 1 (128 -> 128) in two j-halves --------
        uint32_t A2H[32], A2L[32];
        #pragma unroll
        for (int jh = 0; jh < 2; jh++) {
            float acc[32];
            #pragma unroll
            for (int i = 0; i < 32; i++) acc[i] = 0.0f;
            #pragma unroll
            for (int s = 0; s < 8; s++) {
                #pragma unroll
                for (int jj = 0; jj < 8; jj++) {
                    const int j = jh * 8 + jj;
                    uint4 b = BF1[(j * 8 + s) * 32 + lane];
                    float* c = acc + jj * 4;
                    mma_bf16(c, A1H + s * 4, b.x, b.y);
                    mma_bf16(c, A1H + s * 4, b.z, b.w);
                    mma_bf16(c, A1L + s * 4, b.x, b.y);
                }
            }
            #pragma unroll
            for (int jj = 0; jj < 8; jj++) {
                const int j = jh * 8 + jj;
                float2 bb = *(const float2*)(BIAS1 + j * 8 + 2 * cb);
                const int idx = (j >> 1) * 4 + (j & 1) * 2;
                cvt_frag(acc + jj * 4, bb.x, bb.y, bb.x, bb.y,
                         A2H[idx], A2H[idx + 1], A2L[idx], A2L[idx + 1]);
            }
        }

        // -------- layer 2: 128 -> 3 (n padded to 8) --------
        float C2[4] = {0.f, 0.f, 0.f, 0.f};
        #pragma unroll
        for (int s = 0; s < 8; s++) {
            uint4 b = BF2[s * 32 + lane];
            mma_bf16(C2, A2H + s * 4, b.x, b.y);
            mma_bf16(C2, A2H + s * 4, b.z, b.w);
            mma_bf16(C2, A2L + s * 4, b.x, b.y);
        }

        // -------- output --------
        {
            const int p0 = tb + r;
            const int p1 = p0 + 8;
            if (cb == 0) {
                if (p0 < total) {
                    out[(long)p0*3 + 0] = C2[0] + BIAS2[0];
                    out[(long)p0*3 + 1] = C2[1] + BIAS2[1];
                }
                if (p1 < total) {
                    out[(long)p1*3 + 0] = C2[2] + BIAS2[0];
                    out[(long)p1*3 + 1] = C2[3] + BIAS2[1];
                }
            } else if (cb == 1) {
                if (p0 < total) out[(long)p0*3 + 2] = C2[0] + BIAS2[2];
                if (p1 < total) out[(long)p1*3 + 2] = C2[2] + BIAS2[2];
            }
        }
    }
}

extern "C" void kernel_launch(void* const* d_in, const int* in_sizes, int n_in,
                              void* d_out, int out_size)
{
    const float* features    = (const float*)d_in[0];
    const float* dirs        = (const float*)d_in[1];
    const float* embed_table = (const float*)d_in[2];
    const float* W0          = (const float*)d_in[3];
    const float* b0          = (const float*)d_in[4];
    const float* W1          = (const float*)d_in[5];
    const float* b1          = (const float*)d_in[6];
    const float* W2          = (const float*)d_in[7];
    const float* b2          = (const float*)d_in[8];
    const int*   embed_ids   = (const int*)d_in[9];
    const int*   sh_degree_p = (n_in > 10) ? (const int*)d_in[10] : nullptr;
    float* out = (float*)d_out;

    const int C = in_sizes[9];
    const int N = in_sizes[1] / (3 * C);
    const int total = C * N;
    const int ntiles = (total + TILE - 1) / TILE;
    const int cta_tiles = (ntiles + NW - 1) / NW;

    int dev = 0, sms = 148;
    cudaGetDevice(&dev);
    cudaDeviceGetAttribute(&sms, cudaDevAttrMultiProcessorCount, dev);
    int grid = sms < cta_tiles ? sms : cta_tiles;

    const size_t smem_bytes = (size_t)U_TOTAL * 4;
    cudaFuncSetAttribute(vdc_mlp_regpipe12_kernel,
                         cudaFuncAttributeMaxDynamicSharedMemorySize, (int)smem_bytes);

    vdc_mlp_regpipe12_kernel<<<grid, THREADS, smem_bytes>>>(
        features, dirs, embed_table, W0, b0, W1, b1, W2, b2,
        embed_ids, sh_degree_p, out, C, N);
}